// round 2
// baseline (speedup 1.0000x reference)
#include <cuda_runtime.h>
#include <math.h>

#define N_NODES 25000
#define N_EDGES 400000
#define HID 128

// Output float offsets: h, v, f, angular_info, dihedral_info, direction_units
#define OUT_H   0
#define OUT_V   3200000
#define OUT_F   12800000
#define OUT_ANG 64000000
#define OUT_DIH 67200000
#define OUT_DU  118400000

__device__ float4 g_uvec[N_EDGES];           // unit vec xyz + cutoff weight
__device__ float  g_dih[N_EDGES];
__device__ float  g_smsg[(size_t)N_EDGES * HID];
__device__ float  g_Sang[HID];
__device__ float  g_Sdih[HID];

union F2 { unsigned long long u; float2 f; };

__device__ __forceinline__ unsigned long long pack2(float x) {
    unsigned long long r;
    asm("mov.b64 %0, {%1, %1};" : "=l"(r) : "r"(__float_as_uint(x)));
    return r;
}
__device__ __forceinline__ void ffma2(unsigned long long &d, unsigned long long a, unsigned long long b) {
    asm("fma.rn.f32x2 %0, %1, %2, %0;" : "+l"(d) : "l"(a), "l"(b));
}
__device__ __forceinline__ float sigmoid_(float x) { return 1.0f / (1.0f + __expf(-x)); }

// ---------------------------------------------------------------------------
__global__ void k_init(const float* __restrict__ v, float* __restrict__ out) {
    int i = blockIdx.x * blockDim.x + threadIdx.x;
    if (i < 2400000) {
        ((float4*)(out + OUT_V))[i] = ((const float4*)v)[i];
    } else {
        int j = i - 2400000;
        if (j < N_NODES * 3) out[OUT_DU + j] = 0.0f;
    }
}

__global__ void k_colsum(const float* __restrict__ Wang, const float* __restrict__ Wdih) {
    int t = threadIdx.x;
    const float* W = (t < HID) ? Wang : Wdih;
    int c = t & (HID - 1);
    float s = 0.0f;
    for (int k = 0; k < HID; k++) s += W[k * HID + c];
    if (t < HID) g_Sang[c] = s; else g_Sdih[c] = s;
}

__global__ void k_edge_geom(const float* __restrict__ pos, const int* __restrict__ ei,
                            float* __restrict__ out) {
    int e = blockIdx.x * blockDim.x + threadIdx.x;
    if (e >= N_EDGES) return;
    int r = ei[e], c = ei[N_EDGES + e];
    float dx = pos[c*3+0] - pos[r*3+0];
    float dy = pos[c*3+1] - pos[r*3+1];
    float dz = pos[c*3+2] - pos[r*3+2];
    float dist = sqrtf(dx*dx + dy*dy + dz*dz) + 1e-8f;
    float inv = 1.0f / dist;
    float ux = dx*inv, uy = dy*inv, uz = dz*inv;
    float cw = (dist < 10.0f) ? (0.5f * (cosf(0.31415926535897932f * dist) + 1.0f)) : 0.0f;
    g_uvec[e] = make_float4(ux, uy, uz, cw);
    float* du = out + OUT_DU;
    atomicAdd(&du[r*3+0],  ux); atomicAdd(&du[r*3+1],  uy); atomicAdd(&du[r*3+2],  uz);
    atomicAdd(&du[c*3+0], -ux); atomicAdd(&du[c*3+1], -uy); atomicAdd(&du[c*3+2], -uz);
}

__global__ void k_dih(const int* __restrict__ ei, const float* __restrict__ out) {
    int e = blockIdx.x * blockDim.x + threadIdx.x;
    if (e >= N_EDGES) return;
    int r = ei[e], c = ei[N_EDGES + e];
    const float* du = out + OUT_DU;
    float4 u = g_uvec[e];
    float vix = du[r*3+0], viy = du[r*3+1], viz = du[r*3+2];
    float vjx = du[c*3+0], vjy = du[c*3+1], vjz = du[c*3+2];
    float di = vix*u.x + viy*u.y + viz*u.z;
    float dj = vjx*u.x + vjy*u.y + vjz*u.z;
    float wix = vix - di*u.x, wiy = viy - di*u.y, wiz = viz - di*u.z;
    float wjx = vjx - dj*u.x, wjy = vjy - dj*u.y, wjz = vjz - dj*u.z;
    g_dih[e] = wix*wjx + wiy*wjy + wiz*wjz;
}

// ---------------------------------------------------------------------------
// h_updated + angular_info.  128x128 tile, K=128, 256 thr, 8x8/thread FFMA2.
// ---------------------------------------------------------------------------
__global__ __launch_bounds__(256, 2)
void k_node(const float* __restrict__ h, const float* __restrict__ Ws,
            const float* __restrict__ bs, const float* __restrict__ ba,
            float* __restrict__ out) {
    __shared__ __align__(16) float sA[2][8][132];
    __shared__ __align__(16) float sB[2][8][128];
    int tid = threadIdx.x;
    int tx = tid & 15, ty = tid >> 4;
    int m0 = blockIdx.x * 128;
    int lm = tid >> 1, lkq = tid & 1;
    int bk = tid >> 5, bc = (tid & 31) * 4;

    F2 acc[4][8];
#pragma unroll
    for (int p = 0; p < 4; p++)
#pragma unroll
        for (int j = 0; j < 8; j++) acc[p][j].u = 0ULL;

    {
        int n = m0 + lm; if (n >= N_NODES) n = N_NODES - 1;
        float4 av = *(const float4*)&h[(size_t)n * HID + lkq*4];
        float4 bv = *(const float4*)&Ws[(size_t)bk * HID + bc];
        sA[0][lkq*4+0][lm] = av.x; sA[0][lkq*4+1][lm] = av.y;
        sA[0][lkq*4+2][lm] = av.z; sA[0][lkq*4+3][lm] = av.w;
        *(float4*)&sB[0][bk][bc] = bv;
    }
    __syncthreads();

#pragma unroll 1
    for (int kc = 0; kc < 16; kc++) {
        int cb = kc & 1, nb = cb ^ 1;
        float4 av2 = make_float4(0,0,0,0), bv2 = make_float4(0,0,0,0);
        if (kc < 15) {
            int k0 = (kc + 1) * 8;
            int n = m0 + lm; if (n >= N_NODES) n = N_NODES - 1;
            av2 = *(const float4*)&h[(size_t)n * HID + k0 + lkq*4];
            bv2 = *(const float4*)&Ws[(size_t)(k0 + bk) * HID + bc];
        }
#pragma unroll
        for (int kk = 0; kk < 8; kk++) {
            ulonglong2 a01 = *(ulonglong2*)&sA[cb][kk][ty*8];
            ulonglong2 a23 = *(ulonglong2*)&sA[cb][kk][ty*8+4];
            float4 b0 = *(float4*)&sB[cb][kk][tx*8];
            float4 b1 = *(float4*)&sB[cb][kk][tx*8+4];
            unsigned long long ap[4] = {a01.x, a01.y, a23.x, a23.y};
            unsigned long long bp[8] = {pack2(b0.x), pack2(b0.y), pack2(b0.z), pack2(b0.w),
                                        pack2(b1.x), pack2(b1.y), pack2(b1.z), pack2(b1.w)};
#pragma unroll
            for (int p = 0; p < 4; p++)
#pragma unroll
                for (int j = 0; j < 8; j++) ffma2(acc[p][j].u, ap[p], bp[j]);
        }
        if (kc < 15) {
            sA[nb][lkq*4+0][lm] = av2.x; sA[nb][lkq*4+1][lm] = av2.y;
            sA[nb][lkq*4+2][lm] = av2.z; sA[nb][lkq*4+3][lm] = av2.w;
            *(float4*)&sB[nb][bk][bc] = bv2;
        }
        __syncthreads();
    }

    int c0 = tx * 8;
    float bsA[8], saA[8], baA[8];
    *(float4*)&bsA[0] = *(const float4*)&bs[c0];     *(float4*)&bsA[4] = *(const float4*)&bs[c0+4];
    *(float4*)&saA[0] = *(const float4*)&g_Sang[c0]; *(float4*)&saA[4] = *(const float4*)&g_Sang[c0+4];
    *(float4*)&baA[0] = *(const float4*)&ba[c0];     *(float4*)&baA[4] = *(const float4*)&ba[c0+4];
    const float* du = out + OUT_DU;
#pragma unroll
    for (int p = 0; p < 4; p++)
#pragma unroll
        for (int hf = 0; hf < 2; hf++) {
            int n = m0 + ty*8 + p*2 + hf;
            if (n >= N_NODES) continue;
            float ax = du[n*3+0], ay = du[n*3+1], az = du[n*3+2];
            float ang = ax*ax + ay*ay + az*az;
            float hr[8];
            *(float4*)&hr[0] = *(const float4*)&h[(size_t)n*HID + c0];
            *(float4*)&hr[4] = *(const float4*)&h[(size_t)n*HID + c0+4];
            float ov[8];
#pragma unroll
            for (int j = 0; j < 8; j++) {
                float g = hf ? acc[p][j].f.y : acc[p][j].f.x;
                ov[j] = hr[j] + (g + bsA[j]) * sigmoid_(ang * saA[j] + baA[j]);
            }
            *(float4*)&out[OUT_H + (size_t)n*HID + c0]   = *(float4*)&ov[0];
            *(float4*)&out[OUT_H + (size_t)n*HID + c0+4] = *(float4*)&ov[4];
            float4 a4 = make_float4(ang, ang, ang, ang);
            *(float4*)&out[OUT_ANG + (size_t)n*HID + c0]   = a4;
            *(float4*)&out[OUT_ANG + (size_t)n*HID + c0+4] = a4;
        }
}

// ---------------------------------------------------------------------------
// f_updated + dihedral_info.  Same tiling (E is multiple of 128).
// ---------------------------------------------------------------------------
__global__ __launch_bounds__(256, 2)
void k_fgemm(const float* __restrict__ f, const float* __restrict__ We,
             const float* __restrict__ be, const float* __restrict__ bd,
             float* __restrict__ out) {
    __shared__ __align__(16) float sA[2][8][132];
    __shared__ __align__(16) float sB[2][8][128];
    int tid = threadIdx.x;
    int tx = tid & 15, ty = tid >> 4;
    int m0 = blockIdx.x * 128;
    int lm = tid >> 1, lkq = tid & 1;
    int bk = tid >> 5, bc = (tid & 31) * 4;

    F2 acc[4][8];
#pragma unroll
    for (int p = 0; p < 4; p++)
#pragma unroll
        for (int j = 0; j < 8; j++) acc[p][j].u = 0ULL;

    {
        float4 av = *(const float4*)&f[(size_t)(m0+lm) * HID + lkq*4];
        float4 bv = *(const float4*)&We[(size_t)bk * HID + bc];
        sA[0][lkq*4+0][lm] = av.x; sA[0][lkq*4+1][lm] = av.y;
        sA[0][lkq*4+2][lm] = av.z; sA[0][lkq*4+3][lm] = av.w;
        *(float4*)&sB[0][bk][bc] = bv;
    }
    __syncthreads();

#pragma unroll 1
    for (int kc = 0; kc < 16; kc++) {
        int cb = kc & 1, nb = cb ^ 1;
        float4 av2 = make_float4(0,0,0,0), bv2 = make_float4(0,0,0,0);
        if (kc < 15) {
            int k0 = (kc + 1) * 8;
            av2 = *(const float4*)&f[(size_t)(m0+lm) * HID + k0 + lkq*4];
            bv2 = *(const float4*)&We[(size_t)(k0 + bk) * HID + bc];
        }
#pragma unroll
        for (int kk = 0; kk < 8; kk++) {
            ulonglong2 a01 = *(ulonglong2*)&sA[cb][kk][ty*8];
            ulonglong2 a23 = *(ulonglong2*)&sA[cb][kk][ty*8+4];
            float4 b0 = *(float4*)&sB[cb][kk][tx*8];
            float4 b1 = *(float4*)&sB[cb][kk][tx*8+4];
            unsigned long long ap[4] = {a01.x, a01.y, a23.x, a23.y};
            unsigned long long bp[8] = {pack2(b0.x), pack2(b0.y), pack2(b0.z), pack2(b0.w),
                                        pack2(b1.x), pack2(b1.y), pack2(b1.z), pack2(b1.w)};
#pragma unroll
            for (int p = 0; p < 4; p++)
#pragma unroll
                for (int j = 0; j < 8; j++) ffma2(acc[p][j].u, ap[p], bp[j]);
        }
        if (kc < 15) {
            sA[nb][lkq*4+0][lm] = av2.x; sA[nb][lkq*4+1][lm] = av2.y;
            sA[nb][lkq*4+2][lm] = av2.z; sA[nb][lkq*4+3][lm] = av2.w;
            *(float4*)&sB[nb][bk][bc] = bv2;
        }
        __syncthreads();
    }

    int c0 = tx * 8;
    float beA[8], sdA[8], bdA[8];
    *(float4*)&beA[0] = *(const float4*)&be[c0];     *(float4*)&beA[4] = *(const float4*)&be[c0+4];
    *(float4*)&sdA[0] = *(const float4*)&g_Sdih[c0]; *(float4*)&sdA[4] = *(const float4*)&g_Sdih[c0+4];
    *(float4*)&bdA[0] = *(const float4*)&bd[c0];     *(float4*)&bdA[4] = *(const float4*)&bd[c0+4];
#pragma unroll
    for (int p = 0; p < 4; p++)
#pragma unroll
        for (int hf = 0; hf < 2; hf++) {
            int e = m0 + ty*8 + p*2 + hf;
            float dih = g_dih[e];
            float fr[8];
            *(float4*)&fr[0] = *(const float4*)&f[(size_t)e*HID + c0];
            *(float4*)&fr[4] = *(const float4*)&f[(size_t)e*HID + c0+4];
            float ov[8];
#pragma unroll
            for (int j = 0; j < 8; j++) {
                float g = hf ? acc[p][j].f.y : acc[p][j].f.x;
                ov[j] = fr[j] + (g + beA[j]) * sigmoid_(dih * sdA[j] + bdA[j]);
            }
            *(float4*)&out[OUT_F + (size_t)e*HID + c0]   = *(float4*)&ov[0];
            *(float4*)&out[OUT_F + (size_t)e*HID + c0+4] = *(float4*)&ov[4];
            float4 d4 = make_float4(dih, dih, dih, dih);
            *(float4*)&out[OUT_DIH + (size_t)e*HID + c0]   = d4;
            *(float4*)&out[OUT_DIH + (size_t)e*HID + c0+4] = d4;
        }
}

// ---------------------------------------------------------------------------
// scalar_msg = [h[col], h[row], rbf] @ W_msg + b_msg   (K = 306, padded 312)
// ---------------------------------------------------------------------------
__global__ __launch_bounds__(256, 2)
void k_msg_gemm(const float* __restrict__ h, const float* __restrict__ rbf,
                const int* __restrict__ ei, const float* __restrict__ Wm,
                const float* __restrict__ bm) {
    __shared__ __align__(16) float sA[2][8][132];
    __shared__ __align__(16) float sB[2][8][128];
    __shared__ int sRow[128], sCol[128];
    int tid = threadIdx.x;
    int tx = tid & 15, ty = tid >> 4;
    int m0 = blockIdx.x * 128;
    int lm = tid >> 1, lkq = tid & 1;
    int bk = tid >> 5, bc = (tid & 31) * 4;

    if (tid < 128) { sRow[tid] = ei[m0 + tid]; sCol[tid] = ei[N_EDGES + m0 + tid]; }
    __syncthreads();

    F2 acc[4][8];
#pragma unroll
    for (int p = 0; p < 4; p++)
#pragma unroll
        for (int j = 0; j < 8; j++) acc[p][j].u = 0ULL;

    auto loadA = [&](int k0) -> float4 {
        int k = k0 + lkq * 4;
        if (k < 128) {
            return *(const float4*)&h[(size_t)sCol[lm] * HID + k];
        } else if (k < 256) {
            return *(const float4*)&h[(size_t)sRow[lm] * HID + (k - 128)];
        } else {
            int e = m0 + lm;
            float t[4];
#pragma unroll
            for (int i = 0; i < 4; i++) {
                int kk2 = k + i - 256;
                t[i] = (kk2 < 50) ? rbf[(size_t)e * 50 + kk2] : 0.0f;
            }
            return make_float4(t[0], t[1], t[2], t[3]);
        }
    };
    auto loadB = [&](int k0) -> float4 {
        int kg = k0 + bk;
        return (kg < 306) ? *(const float4*)&Wm[(size_t)kg * HID + bc] : make_float4(0,0,0,0);
    };

    {
        float4 av = loadA(0);
        float4 bv = loadB(0);
        sA[0][lkq*4+0][lm] = av.x; sA[0][lkq*4+1][lm] = av.y;
        sA[0][lkq*4+2][lm] = av.z; sA[0][lkq*4+3][lm] = av.w;
        *(float4*)&sB[0][bk][bc] = bv;
    }
    __syncthreads();

#pragma unroll 1
    for (int kc = 0; kc < 39; kc++) {
        int cb = kc & 1, nb = cb ^ 1;
        float4 av2 = make_float4(0,0,0,0), bv2 = make_float4(0,0,0,0);
        if (kc < 38) {
            av2 = loadA((kc + 1) * 8);
            bv2 = loadB((kc + 1) * 8);
        }
#pragma unroll
        for (int kk = 0; kk < 8; kk++) {
            ulonglong2 a01 = *(ulonglong2*)&sA[cb][kk][ty*8];
            ulonglong2 a23 = *(ulonglong2*)&sA[cb][kk][ty*8+4];
            float4 b0 = *(float4*)&sB[cb][kk][tx*8];
            float4 b1 = *(float4*)&sB[cb][kk][tx*8+4];
            unsigned long long ap[4] = {a01.x, a01.y, a23.x, a23.y};
            unsigned long long bp[8] = {pack2(b0.x), pack2(b0.y), pack2(b0.z), pack2(b0.w),
                                        pack2(b1.x), pack2(b1.y), pack2(b1.z), pack2(b1.w)};
#pragma unroll
            for (int p = 0; p < 4; p++)
#pragma unroll
                for (int j = 0; j < 8; j++) ffma2(acc[p][j].u, ap[p], bp[j]);
        }
        if (kc < 38) {
            sA[nb][lkq*4+0][lm] = av2.x; sA[nb][lkq*4+1][lm] = av2.y;
            sA[nb][lkq*4+2][lm] = av2.z; sA[nb][lkq*4+3][lm] = av2.w;
            *(float4*)&sB[nb][bk][bc] = bv2;
        }
        __syncthreads();
    }

    int c0 = tx * 8;
    float bmA[8];
    *(float4*)&bmA[0] = *(const float4*)&bm[c0];
    *(float4*)&bmA[4] = *(const float4*)&bm[c0+4];
#pragma unroll
    for (int p = 0; p < 4; p++)
#pragma unroll
        for (int hf = 0; hf < 2; hf++) {
            int e = m0 + ty*8 + p*2 + hf;
            float ov[8];
#pragma unroll
            for (int j = 0; j < 8; j++) {
                float g = hf ? acc[p][j].f.y : acc[p][j].f.x;
                ov[j] = g + bmA[j];
            }
            *(float4*)&g_smsg[(size_t)e*HID + c0]   = *(float4*)&ov[0];
            *(float4*)&g_smsg[(size_t)e*HID + c0+4] = *(float4*)&ov[4];
        }
}

// ---------------------------------------------------------------------------
// vec_weights = scalar_msg @ W_vec + b_vec; vec_msg; scatter-add into v_upd.
// Tile: 64 edges x 256 cols; each thread owns cols {tx*4..+3} & {128+tx*4..+3}.
// ---------------------------------------------------------------------------
__global__ __launch_bounds__(256, 2)
void k_vec_gemm(const float* __restrict__ Wv, const float* __restrict__ bvp,
                const float* __restrict__ v, const int* __restrict__ ei,
                float* __restrict__ out) {
    __shared__ __align__(16) float sA[2][8][68];
    __shared__ __align__(16) float sB[2][8][256];
    __shared__ int sRow[64], sCol[64];
    int tid = threadIdx.x;
    int tx = tid & 31, ty = tid >> 5;
    int m0 = blockIdx.x * 64;
    int lm = tid >> 1, lkq = tid & 1;            // A loader (tid < 128)
    int b0k = tid >> 6, b0c = (tid & 63) * 4;
    int b1k = 4 + (tid >> 6), b1c = (tid & 63) * 4;

    if (tid < 64) { sRow[tid] = ei[m0 + tid]; sCol[tid] = ei[N_EDGES + m0 + tid]; }
    __syncthreads();

    F2 acc[4][8];
#pragma unroll
    for (int p = 0; p < 4; p++)
#pragma unroll
        for (int j = 0; j < 8; j++) acc[p][j].u = 0ULL;

    {
        if (tid < 128) {
            float4 av = *(const float4*)&g_smsg[(size_t)(m0+lm) * HID + lkq*4];
            sA[0][lkq*4+0][lm] = av.x; sA[0][lkq*4+1][lm] = av.y;
            sA[0][lkq*4+2][lm] = av.z; sA[0][lkq*4+3][lm] = av.w;
        }
        *(float4*)&sB[0][b0k][b0c] = *(const float4*)&Wv[(size_t)b0k * 256 + b0c];
        *(float4*)&sB[0][b1k][b1c] = *(const float4*)&Wv[(size_t)b1k * 256 + b1c];
    }
    __syncthreads();

#pragma unroll 1
    for (int kc = 0; kc < 16; kc++) {
        int cb = kc & 1, nb = cb ^ 1;
        float4 av2 = make_float4(0,0,0,0), bv2a = make_float4(0,0,0,0), bv2b = make_float4(0,0,0,0);
        if (kc < 15) {
            int k0 = (kc + 1) * 8;
            if (tid < 128)
                av2 = *(const float4*)&g_smsg[(size_t)(m0+lm) * HID + k0 + lkq*4];
            bv2a = *(const float4*)&Wv[(size_t)(k0 + b0k) * 256 + b0c];
            bv2b = *(const float4*)&Wv[(size_t)(k0 + b1k) * 256 + b1c];
        }
#pragma unroll
        for (int kk = 0; kk < 8; kk++) {
            ulonglong2 a01 = *(ulonglong2*)&sA[cb][kk][ty*8];
            ulonglong2 a23 = *(ulonglong2*)&sA[cb][kk][ty*8+4];
            float4 b0 = *(float4*)&sB[cb][kk][tx*4];
            float4 b1 = *(float4*)&sB[cb][kk][128 + tx*4];
            unsigned long long ap[4] = {a01.x, a01.y, a23.x, a23.y};
            unsigned long long bp[8] = {pack2(b0.x), pack2(b0.y), pack2(b0.z), pack2(b0.w),
                                        pack2(b1.x), pack2(b1.y), pack2(b1.z), pack2(b1.w)};
#pragma unroll
            for (int p = 0; p < 4; p++)
#pragma unroll
                for (int j = 0; j < 8; j++) ffma2(acc[p][j].u, ap[p], bp[j]);
        }
        if (kc < 15) {
            if (tid < 128) {
                sA[nb][lkq*4+0][lm] = av2.x; sA[nb][lkq*4+1][lm] = av2.y;
                sA[nb][lkq*4+2][lm] = av2.z; sA[nb][lkq*4+3][lm] = av2.w;
            }
            *(float4*)&sB[nb][b0k][b0c] = bv2a;
            *(float4*)&sB[nb][b1k][b1c] = bv2b;
        }
        __syncthreads();
    }

    float bw1[4], bw2[4];
    *(float4*)&bw1[0] = *(const float4*)&bvp[tx*4];
    *(float4*)&bw2[0] = *(const float4*)&bvp[128 + tx*4];
#pragma unroll
    for (int p = 0; p < 4; p++)
#pragma unroll
        for (int hf = 0; hf < 2; hf++) {
            int el = ty*8 + p*2 + hf;
            int e = m0 + el;
            float4 uv = g_uvec[e];
            int r = sRow[el], c = sCol[el];
            float w1[4], w2[4];
#pragma unroll
            for (int j = 0; j < 4; j++) {
                float g1 = hf ? acc[p][j].f.y   : acc[p][j].f.x;
                float g2 = hf ? acc[p][4+j].f.y : acc[p][4+j].f.x;
                w1[j] = g1 + bw1[j];
                w2[j] = g2 + bw2[j];
            }
            float cw = uv.w;
            float uarr[3] = {uv.x, uv.y, uv.z};
#pragma unroll
            for (int d = 0; d < 3; d++) {
                float4 vv = *(const float4*)&v[(size_t)(r*3 + d) * HID + tx*4];
                float4 m;
                m.x = cw * (w1[0] * uarr[d] + w2[0] * vv.x);
                m.y = cw * (w1[1] * uarr[d] + w2[1] * vv.y);
                m.z = cw * (w1[2] * uarr[d] + w2[2] * vv.z);
                m.w = cw * (w1[3] * uarr[d] + w2[3] * vv.w);
#if __CUDA_ARCH__ >= 900
                atomicAdd((float4*)&out[OUT_V + (size_t)(c*3 + d) * HID + tx*4], m);
#else
                float* dst = &out[OUT_V + (size_t)(c*3 + d) * HID + tx*4];
                atomicAdd(dst+0, m.x); atomicAdd(dst+1, m.y);
                atomicAdd(dst+2, m.z); atomicAdd(dst+3, m.w);
#endif
            }
        }
}

// ---------------------------------------------------------------------------
extern "C" void kernel_launch(void* const* d_in, const int* in_sizes, int n_in,
                              void* d_out, int out_size) {
    const float* h    = (const float*)d_in[0];
    const float* v    = (const float*)d_in[1];
    const float* f    = (const float*)d_in[2];
    const float* pos  = (const float*)d_in[3];
    const float* rbf  = (const float*)d_in[4];
    const int*   ei   = (const int*)  d_in[5];
    const float* Wm   = (const float*)d_in[6];
    const float* bm   = (const float*)d_in[7];
    const float* Wv   = (const float*)d_in[8];
    const float* bv   = (const float*)d_in[9];
    const float* Ws   = (const float*)d_in[10];
    const float* bs   = (const float*)d_in[11];
    const float* We   = (const float*)d_in[12];
    const float* be   = (const float*)d_in[13];
    const float* Wa   = (const float*)d_in[14];
    const float* ba   = (const float*)d_in[15];
    const float* Wd   = (const float*)d_in[16];
    const float* bd   = (const float*)d_in[17];
    float* out = (float*)d_out;

    k_init<<<(2400000 + N_NODES*3 + 255) / 256, 256>>>(v, out);
    k_colsum<<<1, 256>>>(Wa, Wd);
    k_edge_geom<<<(N_EDGES + 255) / 256, 256>>>(pos, ei, out);
    k_dih<<<(N_EDGES + 255) / 256, 256>>>(ei, out);
    k_msg_gemm<<<N_EDGES / 128, 256>>>(h, rbf, ei, Wm, bm);
    k_node<<<(N_NODES + 127) / 128, 256>>>(h, Ws, bs, ba, out);
    k_fgemm<<<N_EDGES / 128, 256>>>(f, We, be, bd, out);
    k_vec_gemm<<<N_EDGES / 64, 256>>>(Wv, bv, v, ei, out);
}

// round 6
// speedup vs baseline: 1.2878x; 1.2878x over previous
#include <cuda_runtime.h>
#include <cstdint>
#include <math.h>

#define N_NODES 25000
#define N_EDGES 400000
#define HID 128

// Output float offsets: h, v, f, angular_info, dihedral_info, direction_units
#define OUT_H   0
#define OUT_V   3200000
#define OUT_F   12800000
#define OUT_ANG 64000000
#define OUT_DIH 67200000
#define OUT_DU  118400000

__device__ float4 g_uvec[N_EDGES];           // unit vec xyz + cutoff weight
__device__ float  g_dih[N_EDGES];
__device__ float  g_smsg[(size_t)N_EDGES * HID];
__device__ float  g_Sang[HID];
__device__ float  g_Sdih[HID];
// Transposed (col-major B) weights, zero-padded K
__device__ float  g_WmT[128 * 320];   // B[n][k] = W_msg[k][n], k<306 else 0
__device__ float  g_WvT[256 * 128];   // B[n][k] = W_vec[k][n]
__device__ float  g_WeT[128 * 128];   // B[n][k] = W_edge[k][n]

// ===================== helpers =====================
union F2 { unsigned long long u; float2 f; };
__device__ __forceinline__ unsigned long long pack2(float x) {
    unsigned long long r;
    asm("mov.b64 %0, {%1, %1};" : "=l"(r) : "r"(__float_as_uint(x)));
    return r;
}
__device__ __forceinline__ void ffma2(unsigned long long &d, unsigned long long a, unsigned long long b) {
    asm("fma.rn.f32x2 %0, %1, %2, %0;" : "+l"(d) : "l"(a), "l"(b));
}
__device__ __forceinline__ float sigmoid_(float x) { return 1.0f / (1.0f + __expf(-x)); }

__device__ __forceinline__ uint32_t cvt_tf32(float x) {
    uint32_t r; asm("cvt.rna.tf32.f32 %0, %1;" : "=r"(r) : "f"(x)); return r;
}
__device__ __forceinline__ void mma_m16n8k8(float* d, const uint32_t* a, const uint32_t* b) {
    asm volatile("mma.sync.aligned.m16n8k8.row.col.f32.tf32.tf32.f32 "
        "{%0,%1,%2,%3}, {%4,%5,%6,%7}, {%8,%9}, {%0,%1,%2,%3};"
        : "+f"(d[0]), "+f"(d[1]), "+f"(d[2]), "+f"(d[3])
        : "r"(a[0]), "r"(a[1]), "r"(a[2]), "r"(a[3]), "r"(b[0]), "r"(b[1]));
}

// ===================== elementwise / prep kernels =====================
__global__ void k_init(const float* __restrict__ v, float* __restrict__ out) {
    int i = blockIdx.x * blockDim.x + threadIdx.x;
    if (i < 2400000) {
        ((float4*)(out + OUT_V))[i] = ((const float4*)v)[i];
    } else {
        int j = i - 2400000;
        if (j < N_NODES * 3) out[OUT_DU + j] = 0.0f;
    }
}

__global__ void k_colsum(const float* __restrict__ Wang, const float* __restrict__ Wdih) {
    int t = threadIdx.x;
    const float* W = (t < HID) ? Wang : Wdih;
    int c = t & (HID - 1);
    float s = 0.0f;
    for (int k = 0; k < HID; k++) s += W[k * HID + c];
    if (t < HID) g_Sang[c] = s; else g_Sdih[c] = s;
}

__global__ void k_transpose(const float* __restrict__ Wm, const float* __restrict__ Wv,
                            const float* __restrict__ We) {
    int t = blockIdx.x * blockDim.x + threadIdx.x;
    if (t < 128 * 320) {
        int n = t / 320, k = t % 320;
        g_WmT[t] = (k < 306) ? Wm[(size_t)k * 128 + n] : 0.0f;
    } else if (t < 128 * 320 + 256 * 128) {
        int t2 = t - 128 * 320;
        int n = t2 / 128, k = t2 % 128;
        g_WvT[t2] = Wv[(size_t)k * 256 + n];
    } else if (t < 128 * 320 + 256 * 128 + 128 * 128) {
        int t3 = t - 128 * 320 - 256 * 128;
        int n = t3 / 128, k = t3 % 128;
        g_WeT[t3] = We[(size_t)k * 128 + n];
    }
}

__global__ void k_edge_geom(const float* __restrict__ pos, const int* __restrict__ ei,
                            float* __restrict__ out) {
    int e = blockIdx.x * blockDim.x + threadIdx.x;
    if (e >= N_EDGES) return;
    int r = ei[e], c = ei[N_EDGES + e];
    float dx = pos[c*3+0] - pos[r*3+0];
    float dy = pos[c*3+1] - pos[r*3+1];
    float dz = pos[c*3+2] - pos[r*3+2];
    float dist = sqrtf(dx*dx + dy*dy + dz*dz) + 1e-8f;
    float inv = 1.0f / dist;
    float ux = dx*inv, uy = dy*inv, uz = dz*inv;
    float cw = (dist < 10.0f) ? (0.5f * (cosf(0.31415926535897932f * dist) + 1.0f)) : 0.0f;
    g_uvec[e] = make_float4(ux, uy, uz, cw);
    float* du = out + OUT_DU;
    atomicAdd(&du[r*3+0],  ux); atomicAdd(&du[r*3+1],  uy); atomicAdd(&du[r*3+2],  uz);
    atomicAdd(&du[c*3+0], -ux); atomicAdd(&du[c*3+1], -uy); atomicAdd(&du[c*3+2], -uz);
}

__global__ void k_dih(const int* __restrict__ ei, const float* __restrict__ out) {
    int e = blockIdx.x * blockDim.x + threadIdx.x;
    if (e >= N_EDGES) return;
    int r = ei[e], c = ei[N_EDGES + e];
    const float* du = out + OUT_DU;
    float4 u = g_uvec[e];
    float vix = du[r*3+0], viy = du[r*3+1], viz = du[r*3+2];
    float vjx = du[c*3+0], vjy = du[c*3+1], vjz = du[c*3+2];
    float di = vix*u.x + viy*u.y + viz*u.z;
    float dj = vjx*u.x + vjy*u.y + vjz*u.z;
    float wix = vix - di*u.x, wiy = viy - di*u.y, wiz = viz - di*u.z;
    float wjx = vjx - dj*u.x, wjy = vjy - dj*u.y, wjz = vjz - dj*u.z;
    g_dih[e] = wix*wjx + wiy*wjy + wiz*wjz;
}

// ===================== node GEMM (small, FFMA2 — proven) =====================
__global__ __launch_bounds__(256, 2)
void k_node(const float* __restrict__ h, const float* __restrict__ Ws,
            const float* __restrict__ bs, const float* __restrict__ ba,
            float* __restrict__ out) {
    __shared__ __align__(16) float sA[2][8][132];
    __shared__ __align__(16) float sB[2][8][128];
    int tid = threadIdx.x;
    int tx = tid & 15, ty = tid >> 4;
    int m0 = blockIdx.x * 128;
    int lm = tid >> 1, lkq = tid & 1;
    int bk = tid >> 5, bc = (tid & 31) * 4;

    F2 acc[4][8];
#pragma unroll
    for (int p = 0; p < 4; p++)
#pragma unroll
        for (int j = 0; j < 8; j++) acc[p][j].u = 0ULL;

    {
        int n = m0 + lm; if (n >= N_NODES) n = N_NODES - 1;
        float4 av = *(const float4*)&h[(size_t)n * HID + lkq*4];
        float4 bv = *(const float4*)&Ws[(size_t)bk * HID + bc];
        sA[0][lkq*4+0][lm] = av.x; sA[0][lkq*4+1][lm] = av.y;
        sA[0][lkq*4+2][lm] = av.z; sA[0][lkq*4+3][lm] = av.w;
        *(float4*)&sB[0][bk][bc] = bv;
    }
    __syncthreads();

#pragma unroll 1
    for (int kc = 0; kc < 16; kc++) {
        int cb = kc & 1, nb = cb ^ 1;
        float4 av2 = make_float4(0,0,0,0), bv2 = make_float4(0,0,0,0);
        if (kc < 15) {
            int k0 = (kc + 1) * 8;
            int n = m0 + lm; if (n >= N_NODES) n = N_NODES - 1;
            av2 = *(const float4*)&h[(size_t)n * HID + k0 + lkq*4];
            bv2 = *(const float4*)&Ws[(size_t)(k0 + bk) * HID + bc];
        }
#pragma unroll
        for (int kk = 0; kk < 8; kk++) {
            ulonglong2 a01 = *(ulonglong2*)&sA[cb][kk][ty*8];
            ulonglong2 a23 = *(ulonglong2*)&sA[cb][kk][ty*8+4];
            float4 b0 = *(float4*)&sB[cb][kk][tx*8];
            float4 b1 = *(float4*)&sB[cb][kk][tx*8+4];
            unsigned long long ap[4] = {a01.x, a01.y, a23.x, a23.y};
            unsigned long long bp[8] = {pack2(b0.x), pack2(b0.y), pack2(b0.z), pack2(b0.w),
                                        pack2(b1.x), pack2(b1.y), pack2(b1.z), pack2(b1.w)};
#pragma unroll
            for (int p = 0; p < 4; p++)
#pragma unroll
                for (int j = 0; j < 8; j++) ffma2(acc[p][j].u, ap[p], bp[j]);
        }
        if (kc < 15) {
            sA[nb][lkq*4+0][lm] = av2.x; sA[nb][lkq*4+1][lm] = av2.y;
            sA[nb][lkq*4+2][lm] = av2.z; sA[nb][lkq*4+3][lm] = av2.w;
            *(float4*)&sB[nb][bk][bc] = bv2;
        }
        __syncthreads();
    }

    int c0 = tx * 8;
    float bsA[8], saA[8], baA[8];
    *(float4*)&bsA[0] = *(const float4*)&bs[c0];     *(float4*)&bsA[4] = *(const float4*)&bs[c0+4];
    *(float4*)&saA[0] = *(const float4*)&g_Sang[c0]; *(float4*)&saA[4] = *(const float4*)&g_Sang[c0+4];
    *(float4*)&baA[0] = *(const float4*)&ba[c0];     *(float4*)&baA[4] = *(const float4*)&ba[c0+4];
    const float* du = out + OUT_DU;
#pragma unroll
    for (int p = 0; p < 4; p++)
#pragma unroll
        for (int hf = 0; hf < 2; hf++) {
            int n = m0 + ty*8 + p*2 + hf;
            if (n >= N_NODES) continue;
            float ax = du[n*3+0], ay = du[n*3+1], az = du[n*3+2];
            float ang = ax*ax + ay*ay + az*az;
            float hr[8];
            *(float4*)&hr[0] = *(const float4*)&h[(size_t)n*HID + c0];
            *(float4*)&hr[4] = *(const float4*)&h[(size_t)n*HID + c0+4];
            float ov[8];
#pragma unroll
            for (int j = 0; j < 8; j++) {
                float g = hf ? acc[p][j].f.y : acc[p][j].f.x;
                ov[j] = hr[j] + (g + bsA[j]) * sigmoid_(ang * saA[j] + baA[j]);
            }
            *(float4*)&out[OUT_H + (size_t)n*HID + c0]   = *(float4*)&ov[0];
            *(float4*)&out[OUT_H + (size_t)n*HID + c0+4] = *(float4*)&ov[4];
            float4 a4 = make_float4(ang, ang, ang, ang);
            *(float4*)&out[OUT_ANG + (size_t)n*HID + c0]   = a4;
            *(float4*)&out[OUT_ANG + (size_t)n*HID + c0+4] = a4;
        }
}

// ===================== tf32 mma.sync GEMM kernels =====================
// A staged [m][36] (row-major, pitch 36 -> conflict-free frag reads),
// B staged [k][P] (col-of-W major, pitch 136/264).
// Warp tile 32x64 via m16n8k8: 2 mtiles x 8 ntiles.

#define PA 36
#define ASZ (128 * PA)         // 4608 floats
#define PB 136
#define BSZ (32 * PB)          // 4352 floats

// ---- msg: g_smsg = [h[col],h[row],rbf] @ W_msg + b_msg  (K=320, 10 chunks) ----
__global__ __launch_bounds__(256, 1)
void k_msg_mma(const float* __restrict__ h, const float* __restrict__ rbf,
               const int* __restrict__ ei, const float* __restrict__ bm) {
    extern __shared__ float sm[];
    const int A0 = 0, A1 = ASZ, B0 = 2*ASZ, B1 = 2*ASZ + BSZ;
    int tid = threadIdx.x, wid = tid >> 5, lane = tid & 31;
    int gid = lane >> 2, tig = lane & 3;
    int m0 = blockIdx.x * 128;
    int m0w = (wid & 3) * 32, n0w = (wid >> 2) * 64;

    int r = tid >> 1, s = tid & 1;      // loader row / 16-col half
    int rI = ei[m0 + r], cI = ei[N_EDGES + m0 + r];

    float d[2][8][4];
#pragma unroll
    for (int mt = 0; mt < 2; mt++)
#pragma unroll
        for (int nt = 0; nt < 8; nt++)
#pragma unroll
            for (int q = 0; q < 4; q++) d[mt][nt][q] = 0.0f;

    float4 va[4], vb[4];
    auto gldA = [&](int c) {
#pragma unroll
        for (int i = 0; i < 4; i++) {
            int cl = s*16 + i*4;            // 0..31 within chunk
            if (c < 8) {
                int node = (c < 4) ? cI : rI;
                va[i] = *(const float4*)&h[(size_t)node * HID + (c & 3)*32 + cl];
            } else {
                float t[4];
#pragma unroll
                for (int j = 0; j < 4; j++) {
                    int rk = (c - 8)*32 + cl + j;
                    t[j] = (rk < 50) ? rbf[(size_t)(m0 + r) * 50 + rk] : 0.0f;
                }
                va[i] = make_float4(t[0], t[1], t[2], t[3]);
            }
        }
#pragma unroll
        for (int i = 0; i < 4; i++)
            vb[i] = *(const float4*)&g_WmT[(size_t)r * 320 + c*32 + s*16 + i*4];
    };
    auto store = [&](int buf) {
        float* a = sm + (buf ? A1 : A0);
        float* b = sm + (buf ? B1 : B0);
#pragma unroll
        for (int i = 0; i < 4; i++)
            *(float4*)&a[r * PA + s*16 + i*4] = va[i];
#pragma unroll
        for (int i = 0; i < 4; i++) {
            int k = s*16 + i*4;
            b[(k+0)*PB + r] = vb[i].x; b[(k+1)*PB + r] = vb[i].y;
            b[(k+2)*PB + r] = vb[i].z; b[(k+3)*PB + r] = vb[i].w;
        }
    };

    gldA(0); store(0); __syncthreads();

#pragma unroll 1
    for (int c = 0; c < 10; c++) {
        int cb = c & 1;
        if (c + 1 < 10) gldA(c + 1);
        const float* a = sm + (cb ? A1 : A0);
        const float* b = sm + (cb ? B1 : B0);
#pragma unroll
        for (int kb = 0; kb < 32; kb += 8) {
            uint32_t af[2][4], bf[8][2];
#pragma unroll
            for (int mt = 0; mt < 2; mt++) {
                int mr = m0w + mt*16 + gid;
                af[mt][0] = cvt_tf32(a[mr * PA + kb + tig]);
                af[mt][1] = cvt_tf32(a[(mr+8) * PA + kb + tig]);
                af[mt][2] = cvt_tf32(a[mr * PA + kb + tig + 4]);
                af[mt][3] = cvt_tf32(a[(mr+8) * PA + kb + tig + 4]);
            }
#pragma unroll
            for (int nt = 0; nt < 8; nt++) {
                int nn = n0w + nt*8 + gid;
                bf[nt][0] = cvt_tf32(b[(kb + tig) * PB + nn]);
                bf[nt][1] = cvt_tf32(b[(kb + tig + 4) * PB + nn]);
            }
#pragma unroll
            for (int mt = 0; mt < 2; mt++)
#pragma unroll
                for (int nt = 0; nt < 8; nt++)
                    mma_m16n8k8(d[mt][nt], af[mt], bf[nt]);
        }
        if (c + 1 < 10) store((c + 1) & 1);
        __syncthreads();
    }

    // stage D -> smem (pitch 132), then coalesced global write
#pragma unroll
    for (int mt = 0; mt < 2; mt++)
#pragma unroll
        for (int nt = 0; nt < 8; nt++) {
            int row = m0w + mt*16 + gid;
            int col = n0w + nt*8 + tig*2;
            *(float2*)&sm[row * 132 + col]       = make_float2(d[mt][nt][0], d[mt][nt][1]);
            *(float2*)&sm[(row + 8) * 132 + col] = make_float2(d[mt][nt][2], d[mt][nt][3]);
        }
    __syncthreads();
    {
        int el = tid >> 1, c0 = (tid & 1) * 64;
#pragma unroll
        for (int jv = 0; jv < 16; jv++) {
            float4 w = *(float4*)&sm[el * 132 + c0 + jv*4];
            float4 bb = ((const float4*)(bm + c0))[jv];
            w.x += bb.x; w.y += bb.y; w.z += bb.z; w.w += bb.w;
            *(float4*)&g_smsg[(size_t)(m0 + el) * HID + c0 + jv*4] = w;
        }
    }
}

// ---- f: f_updated + dihedral_info  (K=128, 4 chunks, N=128) ----
__global__ __launch_bounds__(256, 1)
void k_f_mma(const float* __restrict__ f, const float* __restrict__ be,
             const float* __restrict__ bd, float* __restrict__ out) {
    extern __shared__ float sm[];
    const int A0 = 0, A1 = ASZ, B0 = 2*ASZ, B1 = 2*ASZ + BSZ;
    int tid = threadIdx.x, wid = tid >> 5, lane = tid & 31;
    int gid = lane >> 2, tig = lane & 3;
    int m0 = blockIdx.x * 128;
    int m0w = (wid & 3) * 32, n0w = (wid >> 2) * 64;
    int r = tid >> 1, s = tid & 1;

    float d[2][8][4];
#pragma unroll
    for (int mt = 0; mt < 2; mt++)
#pragma unroll
        for (int nt = 0; nt < 8; nt++)
#pragma unroll
            for (int q = 0; q < 4; q++) d[mt][nt][q] = 0.0f;

    float4 va[4], vb[4];
    auto gld = [&](int c) {
#pragma unroll
        for (int i = 0; i < 4; i++) {
            va[i] = *(const float4*)&f[(size_t)(m0 + r) * HID + c*32 + s*16 + i*4];
            vb[i] = *(const float4*)&g_WeT[(size_t)r * 128 + c*32 + s*16 + i*4];
        }
    };
    auto store = [&](int buf) {
        float* a = sm + (buf ? A1 : A0);
        float* b = sm + (buf ? B1 : B0);
#pragma unroll
        for (int i = 0; i < 4; i++)
            *(float4*)&a[r * PA + s*16 + i*4] = va[i];
#pragma unroll
        for (int i = 0; i < 4; i++) {
            int k = s*16 + i*4;
            b[(k+0)*PB + r] = vb[i].x; b[(k+1)*PB + r] = vb[i].y;
            b[(k+2)*PB + r] = vb[i].z; b[(k+3)*PB + r] = vb[i].w;
        }
    };

    gld(0); store(0); __syncthreads();

#pragma unroll 1
    for (int c = 0; c < 4; c++) {
        int cb = c & 1;
        if (c + 1 < 4) gld(c + 1);
        const float* a = sm + (cb ? A1 : A0);
        const float* b = sm + (cb ? B1 : B0);
#pragma unroll
        for (int kb = 0; kb < 32; kb += 8) {
            uint32_t af[2][4], bf[8][2];
#pragma unroll
            for (int mt = 0; mt < 2; mt++) {
                int mr = m0w + mt*16 + gid;
                af[mt][0] = cvt_tf32(a[mr * PA + kb + tig]);
                af[mt][1] = cvt_tf32(a[(mr+8) * PA + kb + tig]);
                af[mt][2] = cvt_tf32(a[mr * PA + kb + tig + 4]);
                af[mt][3] = cvt_tf32(a[(mr+8) * PA + kb + tig + 4]);
            }
#pragma unroll
            for (int nt = 0; nt < 8; nt++) {
                int nn = n0w + nt*8 + gid;
                bf[nt][0] = cvt_tf32(b[(kb + tig) * PB + nn]);
                bf[nt][1] = cvt_tf32(b[(kb + tig + 4) * PB + nn]);
            }
#pragma unroll
            for (int mt = 0; mt < 2; mt++)
#pragma unroll
                for (int nt = 0; nt < 8; nt++)
                    mma_m16n8k8(d[mt][nt], af[mt], bf[nt]);
        }
        if (c + 1 < 4) store((c + 1) & 1);
        __syncthreads();
    }

#pragma unroll
    for (int mt = 0; mt < 2; mt++)
#pragma unroll
        for (int nt = 0; nt < 8; nt++) {
            int row = m0w + mt*16 + gid;
            int col = n0w + nt*8 + tig*2;
            *(float2*)&sm[row * 132 + col]       = make_float2(d[mt][nt][0], d[mt][nt][1]);
            *(float2*)&sm[(row + 8) * 132 + col] = make_float2(d[mt][nt][2], d[mt][nt][3]);
        }
    __syncthreads();
    {
        int el = tid >> 1, c0 = (tid & 1) * 64;
        int eo = m0 + el;
        float dih = g_dih[eo];
        float4 d4 = make_float4(dih, dih, dih, dih);
#pragma unroll
        for (int jv = 0; jv < 16; jv++) {
            float4 g = *(float4*)&sm[el * 132 + c0 + jv*4];
            float4 bev = ((const float4*)(be + c0))[jv];
            float4 sdv = ((const float4*)(g_Sdih + c0))[jv];
            float4 bdv = ((const float4*)(bd + c0))[jv];
            float4 fv  = *(const float4*)&f[(size_t)eo * HID + c0 + jv*4];
            float4 o;
            o.x = fv.x + (g.x + bev.x) * sigmoid_(dih * sdv.x + bdv.x);
            o.y = fv.y + (g.y + bev.y) * sigmoid_(dih * sdv.y + bdv.y);
            o.z = fv.z + (g.z + bev.z) * sigmoid_(dih * sdv.z + bdv.z);
            o.w = fv.w + (g.w + bev.w) * sigmoid_(dih * sdv.w + bdv.w);
            *(float4*)&out[OUT_F + (size_t)eo * HID + c0 + jv*4] = o;
            *(float4*)&out[OUT_DIH + (size_t)eo * HID + c0 + jv*4] = d4;
        }
    }
}

// ---- vec: 128 edges x 256 cols, 512 threads (16 warps, 4m x 4n) ----
#define PBV 264
#define BSZV (32 * PBV)        // 8448 floats
__global__ __launch_bounds__(512, 1)
void k_vec_mma(const float* __restrict__ bvp, const float* __restrict__ v,
               const int* __restrict__ ei, float* __restrict__ out) {
    extern __shared__ float sm[];
    const int A0 = 0, A1 = ASZ, B0 = 2*ASZ, B1 = 2*ASZ + BSZV;
    int tid = threadIdx.x, wid = tid >> 5, lane = tid & 31;
    int gid = lane >> 2, tig = lane & 3;
    int m0 = blockIdx.x * 128;
    int m0w = (wid & 3) * 32, n0w = (wid >> 2) * 64;

    int ra = tid >> 2, qa = tid & 3;    // A loader: row 0..127, 16B quad
    int nb_ = tid >> 1, sb_ = tid & 1;  // B loader: n 0..255, 16-col half

    float d[2][8][4];
#pragma unroll
    for (int mt = 0; mt < 2; mt++)
#pragma unroll
        for (int nt = 0; nt < 8; nt++)
#pragma unroll
            for (int q = 0; q < 4; q++) d[mt][nt][q] = 0.0f;

    float4 va[2], vb[4];
    auto gld = [&](int c) {
#pragma unroll
        for (int i = 0; i < 2; i++)
            va[i] = *(const float4*)&g_smsg[(size_t)(m0 + ra) * HID + c*32 + qa*4 + i*16];
#pragma unroll
        for (int i = 0; i < 4; i++)
            vb[i] = *(const float4*)&g_WvT[(size_t)nb_ * 128 + c*32 + sb_*16 + i*4];
    };
    auto store = [&](int buf) {
        float* a = sm + (buf ? A1 : A0);
        float* b = sm + (buf ? B1 : B0);
#pragma unroll
        for (int i = 0; i < 2; i++)
            *(float4*)&a[ra * PA + qa*4 + i*16] = va[i];
#pragma unroll
        for (int i = 0; i < 4; i++) {
            int k = sb_*16 + i*4;
            b[(k+0)*PBV + nb_] = vb[i].x; b[(k+1)*PBV + nb_] = vb[i].y;
            b[(k+2)*PBV + nb_] = vb[i].z; b[(k+3)*PBV + nb_] = vb[i].w;
        }
    };

    gld(0); store(0); __syncthreads();

#pragma unroll 1
    for (int c = 0; c < 4; c++) {
        int cb = c & 1;
        if (c + 1 < 4) gld(c + 1);
        const float* a = sm + (cb ? A1 : A0);
        const float* b = sm + (cb ? B1 : B0);
#pragma unroll
        for (int kb = 0; kb < 32; kb += 8) {
            uint32_t af[2][4], bf[8][2];
#pragma unroll
            for (int mt = 0; mt < 2; mt++) {
                int mr = m0w + mt*16 + gid;
                af[mt][0] = cvt_tf32(a[mr * PA + kb + tig]);
                af[mt][1] = cvt_tf32(a[(mr+8) * PA + kb + tig]);
                af[mt][2] = cvt_tf32(a[mr * PA + kb + tig + 4]);
                af[mt][3] = cvt_tf32(a[(mr+8) * PA + kb + tig + 4]);
            }
#pragma unroll
            for (int nt = 0; nt < 8; nt++) {
                int nn = n0w + nt*8 + gid;
                bf[nt][0] = cvt_tf32(b[(kb + tig) * PBV + nn]);
                bf[nt][1] = cvt_tf32(b[(kb + tig + 4) * PBV + nn]);
            }
#pragma unroll
            for (int mt = 0; mt < 2; mt++)
#pragma unroll
                for (int nt = 0; nt < 8; nt++)
                    mma_m16n8k8(d[mt][nt], af[mt], bf[nt]);
        }
        if (c + 1 < 4) store((c + 1) & 1);
        __syncthreads();
    }

    // stage D (all 256 cols) -> smem pitch 260
#pragma unroll
    for (int mt = 0; mt < 2; mt++)
#pragma unroll
        for (int nt = 0; nt < 8; nt++) {
            int row = m0w + mt*16 + gid;
            int col = n0w + nt*8 + tig*2;
            *(float2*)&sm[row * 260 + col]       = make_float2(d[mt][nt][0], d[mt][nt][1]);
            *(float2*)&sm[(row + 8) * 260 + col] = make_float2(d[mt][nt][2], d[mt][nt][3]);
        }
    __syncthreads();

    // epilogue: 4 threads per edge, float4-j groups, float4 atomics
    {
        int el = tid >> 2, q = tid & 3;
        int eo = m0 + el;
        int rI = ei[eo], cI = ei[N_EDGES + eo];
        float4 uv = g_uvec[eo];
        float cw = uv.w;
        float ua[3] = {uv.x, uv.y, uv.z};
#pragma unroll
        for (int jv = 0; jv < 8; jv++) {
            int j0 = q*4 + jv*16;
            float4 w1 = *(float4*)&sm[el * 260 + j0];
            float4 w2 = *(float4*)&sm[el * 260 + 128 + j0];
            float4 b1 = *(const float4*)&bvp[j0];
            float4 b2 = *(const float4*)&bvp[128 + j0];
            w1.x += b1.x; w1.y += b1.y; w1.z += b1.z; w1.w += b1.w;
            w2.x += b2.x; w2.y += b2.y; w2.z += b2.z; w2.w += b2.w;
#pragma unroll
            for (int dd = 0; dd < 3; dd++) {
                float4 vv = *(const float4*)&v[((size_t)rI * 3 + dd) * HID + j0];
                float u = ua[dd];
                float4 m;
                m.x = cw * (w1.x * u + w2.x * vv.x);
                m.y = cw * (w1.y * u + w2.y * vv.y);
                m.z = cw * (w1.z * u + w2.z * vv.z);
                m.w = cw * (w1.w * u + w2.w * vv.w);
                atomicAdd((float4*)&out[OUT_V + ((size_t)cI * 3 + dd) * HID + j0], m);
            }
        }
    }
}

// ===================== launcher =====================
extern "C" void kernel_launch(void* const* d_in, const int* in_sizes, int n_in,
                              void* d_out, int out_size) {
    const float* h    = (const float*)d_in[0];
    const float* v    = (const float*)d_in[1];
    const float* f    = (const float*)d_in[2];
    const float* pos  = (const float*)d_in[3];
    const float* rbf  = (const float*)d_in[4];
    const int*   ei   = (const int*)  d_in[5];
    const float* Wm   = (const float*)d_in[6];
    const float* bm   = (const float*)d_in[7];
    const float* Wv   = (const float*)d_in[8];
    const float* bv   = (const float*)d_in[9];
    const float* Ws   = (const float*)d_in[10];
    const float* bs   = (const float*)d_in[11];
    const float* We   = (const float*)d_in[12];
    const float* be   = (const float*)d_in[13];
    const float* Wa   = (const float*)d_in[14];
    const float* ba   = (const float*)d_in[15];
    const float* Wd   = (const float*)d_in[16];
    const float* bd   = (const float*)d_in[17];
    float* out = (float*)d_out;

    const int SM_MSG = (2*ASZ + 2*BSZ) * 4;          // 71680 B
    const int SM_VEC = 128 * 260 * 4;                // 133120 B (>= mainloop 104448)
    cudaFuncSetAttribute(k_msg_mma, cudaFuncAttributeMaxDynamicSharedMemorySize, SM_MSG);
    cudaFuncSetAttribute(k_f_mma,   cudaFuncAttributeMaxDynamicSharedMemorySize, SM_MSG);
    cudaFuncSetAttribute(k_vec_mma, cudaFuncAttributeMaxDynamicSharedMemorySize, SM_VEC);

    k_init<<<(2400000 + N_NODES*3 + 255) / 256, 256>>>(v, out);
    k_colsum<<<1, 256>>>(Wa, Wd);
    k_transpose<<<(128*320 + 256*128 + 128*128 + 255) / 256, 256>>>(Wm, Wv, We);
    k_edge_geom<<<(N_EDGES + 255) / 256, 256>>>(pos, ei, out);
    k_dih<<<(N_EDGES + 255) / 256, 256>>>(ei, out);
    k_msg_mma<<<N_EDGES / 128, 256, SM_MSG>>>(h, rbf, ei, bm);
    k_node<<<(N_NODES + 127) / 128, 256>>>(h, Ws, bs, ba, out);
    k_f_mma<<<N_EDGES / 128, 256, SM_MSG>>>(f, be, bd, out);
    k_vec_mma<<<N_EDGES / 128, 512, SM_VEC>>>(bv, v, ei, out);
}

// round 8
// speedup vs baseline: 1.4356x; 1.1148x over previous
#include <cuda_runtime.h>
#include <cstdint>
#include <math.h>

#define N_NODES 25000
#define N_EDGES 400000
#define HID 128

// Output float offsets: h, v, f, angular_info, dihedral_info, direction_units
#define OUT_H   0
#define OUT_V   3200000
#define OUT_F   12800000
#define OUT_ANG 64000000
#define OUT_DIH 67200000
#define OUT_DU  118400000

__device__ float4 g_uvec[N_EDGES];           // unit vec xyz + cutoff weight
__device__ float  g_dih[N_EDGES];
__device__ float  g_smsg[(size_t)N_EDGES * HID];
__device__ float  g_Sang[HID];
__device__ float  g_Sdih[HID];
// Transposed (col-major B) weights, zero-padded K
__device__ float  g_WmT[128 * 320];   // B[n][k] = W_msg[k][n], k<306 else 0
__device__ float  g_WvT[256 * 128];   // B[n][k] = W_vec[k][n]
__device__ float  g_WeT[128 * 128];   // B[n][k] = W_edge[k][n]

// ===================== helpers =====================
union F2 { unsigned long long u; float2 f; };
__device__ __forceinline__ unsigned long long pack2(float x) {
    unsigned long long r;
    asm("mov.b64 %0, {%1, %1};" : "=l"(r) : "r"(__float_as_uint(x)));
    return r;
}
__device__ __forceinline__ void ffma2(unsigned long long &d, unsigned long long a, unsigned long long b) {
    asm("fma.rn.f32x2 %0, %1, %2, %0;" : "+l"(d) : "l"(a), "l"(b));
}
__device__ __forceinline__ float sigmoid_(float x) { return 1.0f / (1.0f + __expf(-x)); }

__device__ __forceinline__ uint32_t cvt_tf32(float x) {
    uint32_t r; asm("cvt.rna.tf32.f32 %0, %1;" : "=r"(r) : "f"(x)); return r;
}
__device__ __forceinline__ void mma_m16n8k8(float* d, const uint32_t* a, const uint32_t* b) {
    asm volatile("mma.sync.aligned.m16n8k8.row.col.f32.tf32.tf32.f32 "
        "{%0,%1,%2,%3}, {%4,%5,%6,%7}, {%8,%9}, {%0,%1,%2,%3};"
        : "+f"(d[0]), "+f"(d[1]), "+f"(d[2]), "+f"(d[3])
        : "r"(a[0]), "r"(a[1]), "r"(a[2]), "r"(a[3]), "r"(b[0]), "r"(b[1]));
}
__device__ __forceinline__ uint32_t smem_u32(const void* p) {
    uint32_t a;
    asm("{ .reg .u64 t; cvta.to.shared.u64 t, %1; cvt.u32.u64 %0, t; }" : "=r"(a) : "l"(p));
    return a;
}
__device__ __forceinline__ void cp16(uint32_t dst, const void* src) {
    asm volatile("cp.async.cg.shared.global [%0], [%1], 16;" :: "r"(dst), "l"(src));
}
// 4-byte cp.async with src-size predication (handles 4B-aligned-only sources like rbf)
__device__ __forceinline__ void cp4z(uint32_t dst, const void* src, int srcbytes) {
    asm volatile("cp.async.ca.shared.global [%0], [%1], 4, %2;" :: "r"(dst), "l"(src), "r"(srcbytes));
}
__device__ __forceinline__ void cp_commit() { asm volatile("cp.async.commit_group;" ::: "memory"); }
template<int N> __device__ __forceinline__ void cp_wait() { asm volatile("cp.async.wait_group %0;" :: "n"(N) : "memory"); }

// ===================== elementwise / prep kernels =====================
__global__ void k_init(const float* __restrict__ v, float* __restrict__ out) {
    int i = blockIdx.x * blockDim.x + threadIdx.x;
    if (i < 2400000) {
        ((float4*)(out + OUT_V))[i] = ((const float4*)v)[i];
    } else {
        int j = i - 2400000;
        if (j < N_NODES * 3) out[OUT_DU + j] = 0.0f;
    }
}

__global__ void k_colsum(const float* __restrict__ Wang, const float* __restrict__ Wdih) {
    int t = threadIdx.x;
    const float* W = (t < HID) ? Wang : Wdih;
    int c = t & (HID - 1);
    float s = 0.0f;
    for (int k = 0; k < HID; k++) s += W[k * HID + c];
    if (t < HID) g_Sang[c] = s; else g_Sdih[c] = s;
}

__global__ void k_transpose(const float* __restrict__ Wm, const float* __restrict__ Wv,
                            const float* __restrict__ We) {
    int t = blockIdx.x * blockDim.x + threadIdx.x;
    if (t < 128 * 320) {
        int n = t / 320, k = t % 320;
        g_WmT[t] = (k < 306) ? Wm[(size_t)k * 128 + n] : 0.0f;
    } else if (t < 128 * 320 + 256 * 128) {
        int t2 = t - 128 * 320;
        int n = t2 / 128, k = t2 % 128;
        g_WvT[t2] = Wv[(size_t)k * 256 + n];
    } else if (t < 128 * 320 + 256 * 128 + 128 * 128) {
        int t3 = t - 128 * 320 - 256 * 128;
        int n = t3 / 128, k = t3 % 128;
        g_WeT[t3] = We[(size_t)k * 128 + n];
    }
}

__global__ void k_edge_geom(const float* __restrict__ pos, const int* __restrict__ ei,
                            float* __restrict__ out) {
    int e = blockIdx.x * blockDim.x + threadIdx.x;
    if (e >= N_EDGES) return;
    int r = ei[e], c = ei[N_EDGES + e];
    float dx = pos[c*3+0] - pos[r*3+0];
    float dy = pos[c*3+1] - pos[r*3+1];
    float dz = pos[c*3+2] - pos[r*3+2];
    float dist = sqrtf(dx*dx + dy*dy + dz*dz) + 1e-8f;
    float inv = 1.0f / dist;
    float ux = dx*inv, uy = dy*inv, uz = dz*inv;
    float cw = (dist < 10.0f) ? (0.5f * (cosf(0.31415926535897932f * dist) + 1.0f)) : 0.0f;
    g_uvec[e] = make_float4(ux, uy, uz, cw);
    float* du = out + OUT_DU;
    atomicAdd(&du[r*3+0],  ux); atomicAdd(&du[r*3+1],  uy); atomicAdd(&du[r*3+2],  uz);
    atomicAdd(&du[c*3+0], -ux); atomicAdd(&du[c*3+1], -uy); atomicAdd(&du[c*3+2], -uz);
}

__global__ void k_dih(const int* __restrict__ ei, const float* __restrict__ out) {
    int e = blockIdx.x * blockDim.x + threadIdx.x;
    if (e >= N_EDGES) return;
    int r = ei[e], c = ei[N_EDGES + e];
    const float* du = out + OUT_DU;
    float4 u = g_uvec[e];
    float vix = du[r*3+0], viy = du[r*3+1], viz = du[r*3+2];
    float vjx = du[c*3+0], vjy = du[c*3+1], vjz = du[c*3+2];
    float di = vix*u.x + viy*u.y + viz*u.z;
    float dj = vjx*u.x + vjy*u.y + vjz*u.z;
    float wix = vix - di*u.x, wiy = viy - di*u.y, wiz = viz - di*u.z;
    float wjx = vjx - dj*u.x, wjy = vjy - dj*u.y, wjz = vjz - dj*u.z;
    g_dih[e] = wix*wjx + wiy*wjy + wiz*wjz;
}

// ===================== node GEMM (small, FFMA2 — proven) =====================
__global__ __launch_bounds__(256, 2)
void k_node(const float* __restrict__ h, const float* __restrict__ Ws,
            const float* __restrict__ bs, const float* __restrict__ ba,
            float* __restrict__ out) {
    __shared__ __align__(16) float sA[2][8][132];
    __shared__ __align__(16) float sB[2][8][128];
    int tid = threadIdx.x;
    int tx = tid & 15, ty = tid >> 4;
    int m0 = blockIdx.x * 128;
    int lm = tid >> 1, lkq = tid & 1;
    int bk = tid >> 5, bc = (tid & 31) * 4;

    F2 acc[4][8];
#pragma unroll
    for (int p = 0; p < 4; p++)
#pragma unroll
        for (int j = 0; j < 8; j++) acc[p][j].u = 0ULL;

    {
        int n = m0 + lm; if (n >= N_NODES) n = N_NODES - 1;
        float4 av = *(const float4*)&h[(size_t)n * HID + lkq*4];
        float4 bv = *(const float4*)&Ws[(size_t)bk * HID + bc];
        sA[0][lkq*4+0][lm] = av.x; sA[0][lkq*4+1][lm] = av.y;
        sA[0][lkq*4+2][lm] = av.z; sA[0][lkq*4+3][lm] = av.w;
        *(float4*)&sB[0][bk][bc] = bv;
    }
    __syncthreads();

#pragma unroll 1
    for (int kc = 0; kc < 16; kc++) {
        int cb = kc & 1, nb = cb ^ 1;
        float4 av2 = make_float4(0,0,0,0), bv2 = make_float4(0,0,0,0);
        if (kc < 15) {
            int k0 = (kc + 1) * 8;
            int n = m0 + lm; if (n >= N_NODES) n = N_NODES - 1;
            av2 = *(const float4*)&h[(size_t)n * HID + k0 + lkq*4];
            bv2 = *(const float4*)&Ws[(size_t)(k0 + bk) * HID + bc];
        }
#pragma unroll
        for (int kk = 0; kk < 8; kk++) {
            ulonglong2 a01 = *(ulonglong2*)&sA[cb][kk][ty*8];
            ulonglong2 a23 = *(ulonglong2*)&sA[cb][kk][ty*8+4];
            float4 b0 = *(float4*)&sB[cb][kk][tx*8];
            float4 b1 = *(float4*)&sB[cb][kk][tx*8+4];
            unsigned long long ap[4] = {a01.x, a01.y, a23.x, a23.y};
            unsigned long long bp[8] = {pack2(b0.x), pack2(b0.y), pack2(b0.z), pack2(b0.w),
                                        pack2(b1.x), pack2(b1.y), pack2(b1.z), pack2(b1.w)};
#pragma unroll
            for (int p = 0; p < 4; p++)
#pragma unroll
                for (int j = 0; j < 8; j++) ffma2(acc[p][j].u, ap[p], bp[j]);
        }
        if (kc < 15) {
            sA[nb][lkq*4+0][lm] = av2.x; sA[nb][lkq*4+1][lm] = av2.y;
            sA[nb][lkq*4+2][lm] = av2.z; sA[nb][lkq*4+3][lm] = av2.w;
            *(float4*)&sB[nb][bk][bc] = bv2;
        }
        __syncthreads();
    }

    int c0 = tx * 8;
    float bsA[8], saA[8], baA[8];
    *(float4*)&bsA[0] = *(const float4*)&bs[c0];     *(float4*)&bsA[4] = *(const float4*)&bs[c0+4];
    *(float4*)&saA[0] = *(const float4*)&g_Sang[c0]; *(float4*)&saA[4] = *(const float4*)&g_Sang[c0+4];
    *(float4*)&baA[0] = *(const float4*)&ba[c0];     *(float4*)&baA[4] = *(const float4*)&ba[c0+4];
    const float* du = out + OUT_DU;
#pragma unroll
    for (int p = 0; p < 4; p++)
#pragma unroll
        for (int hf = 0; hf < 2; hf++) {
            int n = m0 + ty*8 + p*2 + hf;
            if (n >= N_NODES) continue;
            float ax = du[n*3+0], ay = du[n*3+1], az = du[n*3+2];
            float ang = ax*ax + ay*ay + az*az;
            float hr[8];
            *(float4*)&hr[0] = *(const float4*)&h[(size_t)n*HID + c0];
            *(float4*)&hr[4] = *(const float4*)&h[(size_t)n*HID + c0+4];
            float ov[8];
#pragma unroll
            for (int j = 0; j < 8; j++) {
                float g = hf ? acc[p][j].f.y : acc[p][j].f.x;
                ov[j] = hr[j] + (g + bsA[j]) * sigmoid_(ang * saA[j] + baA[j]);
            }
            *(float4*)&out[OUT_H + (size_t)n*HID + c0]   = *(float4*)&ov[0];
            *(float4*)&out[OUT_H + (size_t)n*HID + c0+4] = *(float4*)&ov[4];
            float4 a4 = make_float4(ang, ang, ang, ang);
            *(float4*)&out[OUT_ANG + (size_t)n*HID + c0]   = a4;
            *(float4*)&out[OUT_ANG + (size_t)n*HID + c0+4] = a4;
        }
}

// ===================== tf32 mma.sync GEMMs with cp.async pipelines =====================
// A and B both staged row-major with pitch 36 floats (144B): frag reads are
// bank-conflict-free (pitch mod 32 = 4 -> bank = 4*gid + tig).
#define PA 36
#define STAGE_A_BYTES (128 * PA * 4)          // 18432
#define STAGE_MF (2 * STAGE_A_BYTES)          // msg/f stage: A + B(128 rows)
#define STAGE_V  (STAGE_A_BYTES + 256 * PA * 4)  // vec stage: A + B(256 rows)

// ---- msg: g_smsg = [h[col],h[row],rbf] @ W_msg + b_msg  (K=320, 10 chunks) ----
__global__ __launch_bounds__(256, 2)
void k_msg_mma(const float* __restrict__ h, const float* __restrict__ rbf,
               const int* __restrict__ ei, const float* __restrict__ bm) {
    extern __shared__ char dsm[];
    float* smf = (float*)dsm;
    const uint32_t sbase = smem_u32(dsm);
    int tid = threadIdx.x, wid = tid >> 5, lane = tid & 31;
    int gid = lane >> 2, tig = lane & 3;
    int m0 = blockIdx.x * 128;
    int m0w = (wid & 3) * 32, n0w = (wid >> 2) * 64;

    int r = tid >> 1, s = tid & 1;
    int rI = ei[m0 + r], cI = ei[N_EDGES + m0 + r];

    float d[2][8][4];
#pragma unroll
    for (int mt = 0; mt < 2; mt++)
#pragma unroll
        for (int nt = 0; nt < 8; nt++)
#pragma unroll
            for (int q = 0; q < 4; q++) d[mt][nt][q] = 0.0f;

    auto issue = [&](int c) {
        int st = c % 3;
        uint32_t aDst = sbase + st * STAGE_MF + r * 144 + s * 64;
        uint32_t bDst = aDst + STAGE_A_BYTES;
        if (c < 8) {
            int node = (c < 4) ? cI : rI;
            const float* src = h + (size_t)node * HID + (c & 3) * 32 + s * 16;
#pragma unroll
            for (int i = 0; i < 4; i++) cp16(aDst + i * 16, src + i * 4);
        } else {
            // rbf chunks: rows are 50 floats (200 B) -> only 4B-aligned. Use 4B cp.async.
            const float* rrow = rbf + (size_t)(m0 + r) * 50;
            int kbase = (c - 8) * 32 + s * 16;
#pragma unroll
            for (int i = 0; i < 16; i++) {
                int rk = kbase + i;
                int ok = (rk < 50);
                cp4z(aDst + i * 4, rrow + (ok ? rk : 0), ok ? 4 : 0);
            }
        }
        const float* bsrc = g_WmT + (size_t)r * 320 + c * 32 + s * 16;
#pragma unroll
        for (int i = 0; i < 4; i++) cp16(bDst + i * 16, bsrc + i * 4);
    };

    issue(0); cp_commit();
    issue(1); cp_commit();

#pragma unroll 1
    for (int c = 0; c < 10; c++) {
        if (c + 2 < 10) issue(c + 2);
        cp_commit();
        cp_wait<2>();
        __syncthreads();
        const float* a = smf + (c % 3) * (STAGE_MF / 4);
        const float* b = a + 128 * PA;
#pragma unroll
        for (int kb = 0; kb < 32; kb += 8) {
            uint32_t af[2][4], bf[8][2];
#pragma unroll
            for (int mt = 0; mt < 2; mt++) {
                int mr = m0w + mt*16 + gid;
                af[mt][0] = cvt_tf32(a[mr * PA + kb + tig]);
                af[mt][1] = cvt_tf32(a[(mr+8) * PA + kb + tig]);
                af[mt][2] = cvt_tf32(a[mr * PA + kb + tig + 4]);
                af[mt][3] = cvt_tf32(a[(mr+8) * PA + kb + tig + 4]);
            }
#pragma unroll
            for (int nt = 0; nt < 8; nt++) {
                int nn = n0w + nt*8 + gid;
                bf[nt][0] = cvt_tf32(b[nn * PA + kb + tig]);
                bf[nt][1] = cvt_tf32(b[nn * PA + kb + tig + 4]);
            }
#pragma unroll
            for (int mt = 0; mt < 2; mt++)
#pragma unroll
                for (int nt = 0; nt < 8; nt++)
                    mma_m16n8k8(d[mt][nt], af[mt], bf[nt]);
        }
        __syncthreads();
    }

    // stage D -> smem (pitch 132), then coalesced global write
#pragma unroll
    for (int mt = 0; mt < 2; mt++)
#pragma unroll
        for (int nt = 0; nt < 8; nt++) {
            int row = m0w + mt*16 + gid;
            int col = n0w + nt*8 + tig*2;
            *(float2*)&smf[row * 132 + col]       = make_float2(d[mt][nt][0], d[mt][nt][1]);
            *(float2*)&smf[(row + 8) * 132 + col] = make_float2(d[mt][nt][2], d[mt][nt][3]);
        }
    __syncthreads();
    {
        int el = tid >> 1, c0 = (tid & 1) * 64;
#pragma unroll
        for (int jv = 0; jv < 16; jv++) {
            float4 w = *(float4*)&smf[el * 132 + c0 + jv*4];
            float4 bb = ((const float4*)(bm + c0))[jv];
            w.x += bb.x; w.y += bb.y; w.z += bb.z; w.w += bb.w;
            *(float4*)&g_smsg[(size_t)(m0 + el) * HID + c0 + jv*4] = w;
        }
    }
}

// ---- f: f_updated + dihedral_info  (K=128, 4 chunks, N=128) ----
__global__ __launch_bounds__(256, 2)
void k_f_mma(const float* __restrict__ f, const float* __restrict__ be,
             const float* __restrict__ bd, float* __restrict__ out) {
    extern __shared__ char dsm[];
    float* smf = (float*)dsm;
    const uint32_t sbase = smem_u32(dsm);
    int tid = threadIdx.x, wid = tid >> 5, lane = tid & 31;
    int gid = lane >> 2, tig = lane & 3;
    int m0 = blockIdx.x * 128;
    int m0w = (wid & 3) * 32, n0w = (wid >> 2) * 64;
    int r = tid >> 1, s = tid & 1;

    float d[2][8][4];
#pragma unroll
    for (int mt = 0; mt < 2; mt++)
#pragma unroll
        for (int nt = 0; nt < 8; nt++)
#pragma unroll
            for (int q = 0; q < 4; q++) d[mt][nt][q] = 0.0f;

    auto issue = [&](int c) {
        int st = c % 3;
        uint32_t aDst = sbase + st * STAGE_MF + r * 144 + s * 64;
        uint32_t bDst = aDst + STAGE_A_BYTES;
        const float* asrc = f + (size_t)(m0 + r) * HID + c * 32 + s * 16;
        const float* bsrc = g_WeT + (size_t)r * 128 + c * 32 + s * 16;
#pragma unroll
        for (int i = 0; i < 4; i++) {
            cp16(aDst + i * 16, asrc + i * 4);
            cp16(bDst + i * 16, bsrc + i * 4);
        }
    };

    issue(0); cp_commit();
    issue(1); cp_commit();

#pragma unroll 1
    for (int c = 0; c < 4; c++) {
        if (c + 2 < 4) issue(c + 2);
        cp_commit();
        cp_wait<2>();
        __syncthreads();
        const float* a = smf + (c % 3) * (STAGE_MF / 4);
        const float* b = a + 128 * PA;
#pragma unroll
        for (int kb = 0; kb < 32; kb += 8) {
            uint32_t af[2][4], bf[8][2];
#pragma unroll
            for (int mt = 0; mt < 2; mt++) {
                int mr = m0w + mt*16 + gid;
                af[mt][0] = cvt_tf32(a[mr * PA + kb + tig]);
                af[mt][1] = cvt_tf32(a[(mr+8) * PA + kb + tig]);
                af[mt][2] = cvt_tf32(a[mr * PA + kb + tig + 4]);
                af[mt][3] = cvt_tf32(a[(mr+8) * PA + kb + tig + 4]);
            }
#pragma unroll
            for (int nt = 0; nt < 8; nt++) {
                int nn = n0w + nt*8 + gid;
                bf[nt][0] = cvt_tf32(b[nn * PA + kb + tig]);
                bf[nt][1] = cvt_tf32(b[nn * PA + kb + tig + 4]);
            }
#pragma unroll
            for (int mt = 0; mt < 2; mt++)
#pragma unroll
                for (int nt = 0; nt < 8; nt++)
                    mma_m16n8k8(d[mt][nt], af[mt], bf[nt]);
        }
        __syncthreads();
    }

#pragma unroll
    for (int mt = 0; mt < 2; mt++)
#pragma unroll
        for (int nt = 0; nt < 8; nt++) {
            int row = m0w + mt*16 + gid;
            int col = n0w + nt*8 + tig*2;
            *(float2*)&smf[row * 132 + col]       = make_float2(d[mt][nt][0], d[mt][nt][1]);
            *(float2*)&smf[(row + 8) * 132 + col] = make_float2(d[mt][nt][2], d[mt][nt][3]);
        }
    __syncthreads();
    {
        int el = tid >> 1, c0 = (tid & 1) * 64;
        int eo = m0 + el;
        float dih = g_dih[eo];
        float4 d4 = make_float4(dih, dih, dih, dih);
#pragma unroll
        for (int jv = 0; jv < 16; jv++) {
            float4 g = *(float4*)&smf[el * 132 + c0 + jv*4];
            float4 bev = ((const float4*)(be + c0))[jv];
            float4 sdv = ((const float4*)(g_Sdih + c0))[jv];
            float4 bdv = ((const float4*)(bd + c0))[jv];
            float4 fv  = *(const float4*)&f[(size_t)eo * HID + c0 + jv*4];
            float4 o;
            o.x = fv.x + (g.x + bev.x) * sigmoid_(dih * sdv.x + bdv.x);
            o.y = fv.y + (g.y + bev.y) * sigmoid_(dih * sdv.y + bdv.y);
            o.z = fv.z + (g.z + bev.z) * sigmoid_(dih * sdv.z + bdv.z);
            o.w = fv.w + (g.w + bev.w) * sigmoid_(dih * sdv.w + bdv.w);
            *(float4*)&out[OUT_F + (size_t)eo * HID + c0 + jv*4] = o;
            *(float4*)&out[OUT_DIH + (size_t)eo * HID + c0 + jv*4] = d4;
        }
    }
}

// ---- vec: 128 edges x 256 cols, 512 threads (16 warps, 4m x 4n) ----
__global__ __launch_bounds__(512, 1)
void k_vec_mma(const float* __restrict__ bvp, const float* __restrict__ v,
               const int* __restrict__ ei, float* __restrict__ out) {
    extern __shared__ char dsm[];
    float* smf = (float*)dsm;
    const uint32_t sbase = smem_u32(dsm);
    int tid = threadIdx.x, wid = tid >> 5, lane = tid & 31;
    int gid = lane >> 2, tig = lane & 3;
    int m0 = blockIdx.x * 128;
    int m0w = (wid & 3) * 32, n0w = (wid >> 2) * 64;

    float d[2][8][4];
#pragma unroll
    for (int mt = 0; mt < 2; mt++)
#pragma unroll
        for (int nt = 0; nt < 8; nt++)
#pragma unroll
            for (int q = 0; q < 4; q++) d[mt][nt][q] = 0.0f;

    auto issue = [&](int c) {
        int st = c % 3;
        uint32_t base = sbase + st * STAGE_V;
        // A: 1024 16B-groups (128 rows x 8), 2 per thread
#pragma unroll
        for (int g2 = 0; g2 < 2; g2++) {
            int g = tid + g2 * 512;
            int row = g >> 3, i = g & 7;
            cp16(base + row * 144 + i * 16,
                 g_smsg + (size_t)(m0 + row) * HID + c * 32 + i * 4);
        }
        // B: 2048 groups (256 rows x 8), 4 per thread
#pragma unroll
        for (int g2 = 0; g2 < 4; g2++) {
            int g = tid + g2 * 512;
            int n = g >> 3, i = g & 7;
            cp16(base + STAGE_A_BYTES + n * 144 + i * 16,
                 g_WvT + (size_t)n * 128 + c * 32 + i * 4);
        }
    };

    issue(0); cp_commit();
    issue(1); cp_commit();

#pragma unroll 1
    for (int c = 0; c < 4; c++) {
        if (c + 2 < 4) issue(c + 2);
        cp_commit();
        cp_wait<2>();
        __syncthreads();
        const float* a = smf + (c % 3) * (STAGE_V / 4);
        const float* b = a + 128 * PA;
#pragma unroll
        for (int kb = 0; kb < 32; kb += 8) {
            uint32_t af[2][4], bf[8][2];
#pragma unroll
            for (int mt = 0; mt < 2; mt++) {
                int mr = m0w + mt*16 + gid;
                af[mt][0] = cvt_tf32(a[mr * PA + kb + tig]);
                af[mt][1] = cvt_tf32(a[(mr+8) * PA + kb + tig]);
                af[mt][2] = cvt_tf32(a[mr * PA + kb + tig + 4]);
                af[mt][3] = cvt_tf32(a[(mr+8) * PA + kb + tig + 4]);
            }
#pragma unroll
            for (int nt = 0; nt < 8; nt++) {
                int nn = n0w + nt*8 + gid;
                bf[nt][0] = cvt_tf32(b[nn * PA + kb + tig]);
                bf[nt][1] = cvt_tf32(b[nn * PA + kb + tig + 4]);
            }
#pragma unroll
            for (int mt = 0; mt < 2; mt++)
#pragma unroll
                for (int nt = 0; nt < 8; nt++)
                    mma_m16n8k8(d[mt][nt], af[mt], bf[nt]);
        }
        __syncthreads();
    }

    // stage D (all 256 cols) -> smem pitch 260
#pragma unroll
    for (int mt = 0; mt < 2; mt++)
#pragma unroll
        for (int nt = 0; nt < 8; nt++) {
            int row = m0w + mt*16 + gid;
            int col = n0w + nt*8 + tig*2;
            *(float2*)&smf[row * 260 + col]       = make_float2(d[mt][nt][0], d[mt][nt][1]);
            *(float2*)&smf[(row + 8) * 260 + col] = make_float2(d[mt][nt][2], d[mt][nt][3]);
        }
    __syncthreads();

    // epilogue: 4 threads per edge, float4 atomics
    {
        int el = tid >> 2, q = tid & 3;
        int eo = m0 + el;
        int rI = ei[eo], cI = ei[N_EDGES + eo];
        float4 uv = g_uvec[eo];
        float cw = uv.w;
        float ua[3] = {uv.x, uv.y, uv.z};
#pragma unroll
        for (int jv = 0; jv < 8; jv++) {
            int j0 = q*4 + jv*16;
            float4 w1 = *(float4*)&smf[el * 260 + j0];
            float4 w2 = *(float4*)&smf[el * 260 + 128 + j0];
            float4 b1 = *(const float4*)&bvp[j0];
            float4 b2 = *(const float4*)&bvp[128 + j0];
            w1.x += b1.x; w1.y += b1.y; w1.z += b1.z; w1.w += b1.w;
            w2.x += b2.x; w2.y += b2.y; w2.z += b2.z; w2.w += b2.w;
#pragma unroll
            for (int dd = 0; dd < 3; dd++) {
                float4 vv = *(const float4*)&v[((size_t)rI * 3 + dd) * HID + j0];
                float u = ua[dd];
                float4 m;
                m.x = cw * (w1.x * u + w2.x * vv.x);
                m.y = cw * (w1.y * u + w2.y * vv.y);
                m.z = cw * (w1.z * u + w2.z * vv.z);
                m.w = cw * (w1.w * u + w2.w * vv.w);
                atomicAdd((float4*)&out[OUT_V + ((size_t)cI * 3 + dd) * HID + j0], m);
            }
        }
    }
}

// ===================== launcher =====================
extern "C" void kernel_launch(void* const* d_in, const int* in_sizes, int n_in,
                              void* d_out, int out_size) {
    const float* h    = (const float*)d_in[0];
    const float* v    = (const float*)d_in[1];
    const float* f    = (const float*)d_in[2];
    const float* pos  = (const float*)d_in[3];
    const float* rbf  = (const float*)d_in[4];
    const int*   ei   = (const int*)  d_in[5];
    const float* Wm   = (const float*)d_in[6];
    const float* bm   = (const float*)d_in[7];
    const float* Wv   = (const float*)d_in[8];
    const float* bv   = (const float*)d_in[9];
    const float* Ws   = (const float*)d_in[10];
    const float* bs   = (const float*)d_in[11];
    const float* We   = (const float*)d_in[12];
    const float* be   = (const float*)d_in[13];
    const float* Wa   = (const float*)d_in[14];
    const float* ba   = (const float*)d_in[15];
    const float* Wd   = (const float*)d_in[16];
    const float* bd   = (const float*)d_in[17];
    float* out = (float*)d_out;

    const int SM_MF  = 3 * STAGE_MF;                       // 110592 B (> epi 67584)
    const int SM_VEC = 3 * STAGE_V;                        // 165888 B (> epi 133120)
    cudaFuncSetAttribute(k_msg_mma, cudaFuncAttributeMaxDynamicSharedMemorySize, SM_MF);
    cudaFuncSetAttribute(k_f_mma,   cudaFuncAttributeMaxDynamicSharedMemorySize, SM_MF);
    cudaFuncSetAttribute(k_vec_mma, cudaFuncAttributeMaxDynamicSharedMemorySize, SM_VEC);

    // Launch order chosen so the profiler's captured launch (index 3) is k_msg_mma.
    k_colsum<<<1, 256>>>(Wa, Wd);
    k_transpose<<<(128*320 + 256*128 + 128*128 + 255) / 256, 256>>>(Wm, Wv, We);
    k_init<<<(2400000 + N_NODES*3 + 255) / 256, 256>>>(v, out);
    k_msg_mma<<<N_EDGES / 128, 256, SM_MF>>>(h, rbf, ei, bm);
    k_edge_geom<<<(N_EDGES + 255) / 256, 256>>>(pos, ei, out);
    k_dih<<<(N_EDGES + 255) / 256, 256>>>(ei, out);
    k_node<<<(N_NODES + 127) / 128, 256>>>(h, Ws, bs, ba, out);
    k_f_mma<<<N_EDGES / 128, 256, SM_MF>>>(f, be, bd, out);
    k_vec_mma<<<N_EDGES / 128, 512, SM_VEC>>>(bv, v, ei, out);
}

// round 9
// speedup vs baseline: 1.5640x; 1.0894x over previous
#include <cuda_runtime.h>
#include <cstdint>
#include <math.h>

#define N_NODES 25000
#define N_EDGES 400000
#define HID 128

// Output float offsets: h, v, f, angular_info, dihedral_info, direction_units
#define OUT_H   0
#define OUT_V   3200000
#define OUT_F   12800000
#define OUT_ANG 64000000
#define OUT_DIH 67200000
#define OUT_DU  118400000

__device__ float4 g_uvec[N_EDGES];           // unit vec xyz + cutoff weight
__device__ float  g_dih[N_EDGES];
__device__ float  g_smsg[(size_t)N_EDGES * HID];
__device__ float  g_Sang[HID];
__device__ float  g_Sdih[HID];
// Fragment-major, tf32-pre-rounded B weights:
// layout [chunk][nblock(64)][kb4][lane][16 floats]; value(lane,j) =
//   W[k = c*32 + kb4*8 + (lane&3) + (j&1)*4][n = nb*64 + (j>>1)*8 + (lane>>2)]
__device__ float  g_WmF[10 * 2 * 4 * 32 * 16];   // 40960 (K=320 padded, N=128)
__device__ float  g_WeF[ 4 * 2 * 4 * 32 * 16];   // 16384 (K=128, N=128)
__device__ float  g_WvF[ 4 * 4 * 4 * 32 * 16];   // 32768 (K=128, N=256)

// ===================== helpers =====================
union F2 { unsigned long long u; float2 f; };
__device__ __forceinline__ unsigned long long pack2(float x) {
    unsigned long long r;
    asm("mov.b64 %0, {%1, %1};" : "=l"(r) : "r"(__float_as_uint(x)));
    return r;
}
__device__ __forceinline__ void ffma2(unsigned long long &d, unsigned long long a, unsigned long long b) {
    asm("fma.rn.f32x2 %0, %1, %2, %0;" : "+l"(d) : "l"(a), "l"(b));
}
__device__ __forceinline__ float sigmoid_(float x) { return 1.0f / (1.0f + __expf(-x)); }

__device__ __forceinline__ uint32_t cvt_tf32(float x) {
    uint32_t r; asm("cvt.rna.tf32.f32 %0, %1;" : "=r"(r) : "f"(x)); return r;
}
__device__ __forceinline__ void mma_m16n8k8(float* d, const uint32_t* a, const uint32_t* b) {
    asm volatile("mma.sync.aligned.m16n8k8.row.col.f32.tf32.tf32.f32 "
        "{%0,%1,%2,%3}, {%4,%5,%6,%7}, {%8,%9}, {%0,%1,%2,%3};"
        : "+f"(d[0]), "+f"(d[1]), "+f"(d[2]), "+f"(d[3])
        : "r"(a[0]), "r"(a[1]), "r"(a[2]), "r"(a[3]), "r"(b[0]), "r"(b[1]));
}
__device__ __forceinline__ uint32_t smem_u32(const void* p) {
    uint32_t a;
    asm("{ .reg .u64 t; cvta.to.shared.u64 t, %1; cvt.u32.u64 %0, t; }" : "=r"(a) : "l"(p));
    return a;
}
__device__ __forceinline__ void cp16(uint32_t dst, const void* src) {
    asm volatile("cp.async.cg.shared.global [%0], [%1], 16;" :: "r"(dst), "l"(src));
}
__device__ __forceinline__ void cp4z(uint32_t dst, const void* src, int srcbytes) {
    asm volatile("cp.async.ca.shared.global [%0], [%1], 4, %2;" :: "r"(dst), "l"(src), "r"(srcbytes));
}
__device__ __forceinline__ void cp_commit() { asm volatile("cp.async.commit_group;" ::: "memory"); }
template<int N> __device__ __forceinline__ void cp_wait() { asm volatile("cp.async.wait_group %0;" :: "n"(N) : "memory"); }

// ===================== elementwise / prep kernels =====================
__global__ void k_init(const float* __restrict__ v, float* __restrict__ out) {
    int i = blockIdx.x * blockDim.x + threadIdx.x;
    if (i < 2400000) {
        ((float4*)(out + OUT_V))[i] = ((const float4*)v)[i];
    } else {
        int j = i - 2400000;
        if (j < N_NODES * 3) out[OUT_DU + j] = 0.0f;
    }
}

__global__ void k_colsum(const float* __restrict__ Wang, const float* __restrict__ Wdih) {
    int t = threadIdx.x;
    const float* W = (t < HID) ? Wang : Wdih;
    int c = t & (HID - 1);
    float s = 0.0f;
    for (int k = 0; k < HID; k++) s += W[k * HID + c];
    if (t < HID) g_Sang[c] = s; else g_Sdih[c] = s;
}

// Pack B weights into fragment-major order with tf32 rounding applied.
__global__ void k_fragpack(const float* __restrict__ Wm, const float* __restrict__ Wv,
                           const float* __restrict__ We) {
    int t = blockIdx.x * blockDim.x + threadIdx.x;
    if (t < 40960) {
        int c = t >> 12, rem = t & 4095;
        int lb = rem >> 4, j = rem & 15;
        int nb = lb >> 7, kb4 = (lb >> 5) & 3, lane = lb & 31;
        int n = nb * 64 + (j >> 1) * 8 + (lane >> 2);
        int k = c * 32 + kb4 * 8 + (lane & 3) + (j & 1) * 4;
        float val = (k < 306) ? Wm[(size_t)k * 128 + n] : 0.0f;
        g_WmF[t] = __uint_as_float(cvt_tf32(val));
    } else if (t < 40960 + 16384) {
        int t2 = t - 40960;
        int c = t2 >> 12, rem = t2 & 4095;
        int lb = rem >> 4, j = rem & 15;
        int nb = lb >> 7, kb4 = (lb >> 5) & 3, lane = lb & 31;
        int n = nb * 64 + (j >> 1) * 8 + (lane >> 2);
        int k = c * 32 + kb4 * 8 + (lane & 3) + (j & 1) * 4;
        g_WeF[t2] = __uint_as_float(cvt_tf32(We[(size_t)k * 128 + n]));
    } else if (t < 40960 + 16384 + 32768) {
        int t3 = t - 57344;
        int c = t3 >> 13, rem = t3 & 8191;
        int lb = rem >> 4, j = rem & 15;
        int nb = lb >> 7, kb4 = (lb >> 5) & 3, lane = lb & 31;
        int n = nb * 64 + (j >> 1) * 8 + (lane >> 2);
        int k = c * 32 + kb4 * 8 + (lane & 3) + (j & 1) * 4;
        g_WvF[t3] = __uint_as_float(cvt_tf32(Wv[(size_t)k * 256 + n]));
    }
}

__global__ void k_edge_geom(const float* __restrict__ pos, const int* __restrict__ ei,
                            float* __restrict__ out) {
    int e = blockIdx.x * blockDim.x + threadIdx.x;
    if (e >= N_EDGES) return;
    int r = ei[e], c = ei[N_EDGES + e];
    float dx = pos[c*3+0] - pos[r*3+0];
    float dy = pos[c*3+1] - pos[r*3+1];
    float dz = pos[c*3+2] - pos[r*3+2];
    float dist = sqrtf(dx*dx + dy*dy + dz*dz) + 1e-8f;
    float inv = 1.0f / dist;
    float ux = dx*inv, uy = dy*inv, uz = dz*inv;
    float cw = (dist < 10.0f) ? (0.5f * (cosf(0.31415926535897932f * dist) + 1.0f)) : 0.0f;
    g_uvec[e] = make_float4(ux, uy, uz, cw);
    float* du = out + OUT_DU;
    atomicAdd(&du[r*3+0],  ux); atomicAdd(&du[r*3+1],  uy); atomicAdd(&du[r*3+2],  uz);
    atomicAdd(&du[c*3+0], -ux); atomicAdd(&du[c*3+1], -uy); atomicAdd(&du[c*3+2], -uz);
}

__global__ void k_dih(const int* __restrict__ ei, const float* __restrict__ out) {
    int e = blockIdx.x * blockDim.x + threadIdx.x;
    if (e >= N_EDGES) return;
    int r = ei[e], c = ei[N_EDGES + e];
    const float* du = out + OUT_DU;
    float4 u = g_uvec[e];
    float vix = du[r*3+0], viy = du[r*3+1], viz = du[r*3+2];
    float vjx = du[c*3+0], vjy = du[c*3+1], vjz = du[c*3+2];
    float di = vix*u.x + viy*u.y + viz*u.z;
    float dj = vjx*u.x + vjy*u.y + vjz*u.z;
    float wix = vix - di*u.x, wiy = viy - di*u.y, wiz = viz - di*u.z;
    float wjx = vjx - dj*u.x, wjy = vjy - dj*u.y, wjz = vjz - dj*u.z;
    g_dih[e] = wix*wjx + wiy*wjy + wiz*wjz;
}

// ===================== node GEMM (small, FFMA2 — proven) =====================
__global__ __launch_bounds__(256, 2)
void k_node(const float* __restrict__ h, const float* __restrict__ Ws,
            const float* __restrict__ bs, const float* __restrict__ ba,
            float* __restrict__ out) {
    __shared__ __align__(16) float sA[2][8][132];
    __shared__ __align__(16) float sB[2][8][128];
    int tid = threadIdx.x;
    int tx = tid & 15, ty = tid >> 4;
    int m0 = blockIdx.x * 128;
    int lm = tid >> 1, lkq = tid & 1;
    int bk = tid >> 5, bc = (tid & 31) * 4;

    F2 acc[4][8];
#pragma unroll
    for (int p = 0; p < 4; p++)
#pragma unroll
        for (int j = 0; j < 8; j++) acc[p][j].u = 0ULL;

    {
        int n = m0 + lm; if (n >= N_NODES) n = N_NODES - 1;
        float4 av = *(const float4*)&h[(size_t)n * HID + lkq*4];
        float4 bv = *(const float4*)&Ws[(size_t)bk * HID + bc];
        sA[0][lkq*4+0][lm] = av.x; sA[0][lkq*4+1][lm] = av.y;
        sA[0][lkq*4+2][lm] = av.z; sA[0][lkq*4+3][lm] = av.w;
        *(float4*)&sB[0][bk][bc] = bv;
    }
    __syncthreads();

#pragma unroll 1
    for (int kc = 0; kc < 16; kc++) {
        int cb = kc & 1, nb = cb ^ 1;
        float4 av2 = make_float4(0,0,0,0), bv2 = make_float4(0,0,0,0);
        if (kc < 15) {
            int k0 = (kc + 1) * 8;
            int n = m0 + lm; if (n >= N_NODES) n = N_NODES - 1;
            av2 = *(const float4*)&h[(size_t)n * HID + k0 + lkq*4];
            bv2 = *(const float4*)&Ws[(size_t)(k0 + bk) * HID + bc];
        }
#pragma unroll
        for (int kk = 0; kk < 8; kk++) {
            ulonglong2 a01 = *(ulonglong2*)&sA[cb][kk][ty*8];
            ulonglong2 a23 = *(ulonglong2*)&sA[cb][kk][ty*8+4];
            float4 b0 = *(float4*)&sB[cb][kk][tx*8];
            float4 b1 = *(float4*)&sB[cb][kk][tx*8+4];
            unsigned long long ap[4] = {a01.x, a01.y, a23.x, a23.y};
            unsigned long long bp[8] = {pack2(b0.x), pack2(b0.y), pack2(b0.z), pack2(b0.w),
                                        pack2(b1.x), pack2(b1.y), pack2(b1.z), pack2(b1.w)};
#pragma unroll
            for (int p = 0; p < 4; p++)
#pragma unroll
                for (int j = 0; j < 8; j++) ffma2(acc[p][j].u, ap[p], bp[j]);
        }
        if (kc < 15) {
            sA[nb][lkq*4+0][lm] = av2.x; sA[nb][lkq*4+1][lm] = av2.y;
            sA[nb][lkq*4+2][lm] = av2.z; sA[nb][lkq*4+3][lm] = av2.w;
            *(float4*)&sB[nb][bk][bc] = bv2;
        }
        __syncthreads();
    }

    int c0 = tx * 8;
    float bsA[8], saA[8], baA[8];
    *(float4*)&bsA[0] = *(const float4*)&bs[c0];     *(float4*)&bsA[4] = *(const float4*)&bs[c0+4];
    *(float4*)&saA[0] = *(const float4*)&g_Sang[c0]; *(float4*)&saA[4] = *(const float4*)&g_Sang[c0+4];
    *(float4*)&baA[0] = *(const float4*)&ba[c0];     *(float4*)&baA[4] = *(const float4*)&ba[c0+4];
    const float* du = out + OUT_DU;
#pragma unroll
    for (int p = 0; p < 4; p++)
#pragma unroll
        for (int hf = 0; hf < 2; hf++) {
            int n = m0 + ty*8 + p*2 + hf;
            if (n >= N_NODES) continue;
            float ax = du[n*3+0], ay = du[n*3+1], az = du[n*3+2];
            float ang = ax*ax + ay*ay + az*az;
            float hr[8];
            *(float4*)&hr[0] = *(const float4*)&h[(size_t)n*HID + c0];
            *(float4*)&hr[4] = *(const float4*)&h[(size_t)n*HID + c0+4];
            float ov[8];
#pragma unroll
            for (int j = 0; j < 8; j++) {
                float g = hf ? acc[p][j].f.y : acc[p][j].f.x;
                ov[j] = hr[j] + (g + bsA[j]) * sigmoid_(ang * saA[j] + baA[j]);
            }
            *(float4*)&out[OUT_H + (size_t)n*HID + c0]   = *(float4*)&ov[0];
            *(float4*)&out[OUT_H + (size_t)n*HID + c0+4] = *(float4*)&ov[4];
            float4 a4 = make_float4(ang, ang, ang, ang);
            *(float4*)&out[OUT_ANG + (size_t)n*HID + c0]   = a4;
            *(float4*)&out[OUT_ANG + (size_t)n*HID + c0+4] = a4;
        }
}

// ===================== tf32 mma.sync GEMMs, fragment-major B =====================
// A staged [m][36] floats (conflict-free scalar frag reads).
// B staged fragment-major: per chunk, lane-blocks of 16 floats padded to 80B;
// frag read = 4x LDS.128 per k8, zero cvt (pre-rounded at pack time).
#define STAGE_A_BYTES (128 * 36 * 4)               // 18432
#define BF_MF  (2 * 4 * 32 * 80)                   // 20480 (N=128: 2 nblocks)
#define BF_V   (4 * 4 * 32 * 80)                   // 40960 (N=256: 4 nblocks)
#define STAGE_MF2 (STAGE_A_BYTES + BF_MF)          // 38912
#define STAGE_V3  (STAGE_A_BYTES + BF_V)           // 59392
#define PA 36

// ---- msg: g_smsg = [h[col],h[row],rbf] @ W_msg + b_msg  (K=320, 10 chunks) ----
__global__ __launch_bounds__(256, 2)
void k_msg_mma(const float* __restrict__ h, const float* __restrict__ rbf,
               const int* __restrict__ ei, const float* __restrict__ bm) {
    extern __shared__ char dsm[];
    float* smf = (float*)dsm;
    const uint32_t sbase = smem_u32(dsm);
    int tid = threadIdx.x, wid = tid >> 5, lane = tid & 31;
    int gid = lane >> 2, tig = lane & 3;
    int m0 = blockIdx.x * 128;
    int m0w = (wid & 3) * 32, nb2 = wid >> 2;

    int r = tid >> 1, s = tid & 1;
    int rI = ei[m0 + r], cI = ei[N_EDGES + m0 + r];

    float d[2][8][4];
#pragma unroll
    for (int mt = 0; mt < 2; mt++)
#pragma unroll
        for (int nt = 0; nt < 8; nt++)
#pragma unroll
            for (int q = 0; q < 4; q++) d[mt][nt][q] = 0.0f;

    auto issue = [&](int c) {
        int st = c & 1;
        uint32_t aDst = sbase + st * STAGE_MF2 + r * 144 + s * 64;
        if (c < 8) {
            int node = (c < 4) ? cI : rI;
            const float* src = h + (size_t)node * HID + (c & 3) * 32 + s * 16;
#pragma unroll
            for (int i = 0; i < 4; i++) cp16(aDst + i * 16, src + i * 4);
        } else {
            const float* rrow = rbf + (size_t)(m0 + r) * 50;
            int kbase = (c - 8) * 32 + s * 16;
#pragma unroll
            for (int i = 0; i < 16; i++) {
                int rk = kbase + i;
                int ok = (rk < 50);
                cp4z(aDst + i * 4, rrow + (ok ? rk : 0), ok ? 4 : 0);
            }
        }
        // B: 1024 16B groups; this thread does 4
        uint32_t bBase = sbase + st * STAGE_MF2 + STAGE_A_BYTES;
        const float* bsrc = g_WmF + c * 4096;
#pragma unroll
        for (int t2 = 0; t2 < 4; t2++) {
            int g = tid + t2 * 256;
            int lb = g >> 2, i = g & 3;
            cp16(bBase + lb * 80 + i * 16, bsrc + lb * 16 + i * 4);
        }
    };

    issue(0); cp_commit();

#pragma unroll 1
    for (int c = 0; c < 10; c++) {
        if (c + 1 < 10) issue(c + 1);
        cp_commit();
        cp_wait<1>();
        __syncthreads();
        const float* a = smf + (c & 1) * (STAGE_MF2 / 4);
        const char* bp = dsm + (c & 1) * STAGE_MF2 + STAGE_A_BYTES;
#pragma unroll
        for (int kb4 = 0; kb4 < 4; kb4++) {
            int kb = kb4 * 8;
            uint32_t af[2][4];
#pragma unroll
            for (int mt = 0; mt < 2; mt++) {
                int mr = m0w + mt*16 + gid;
                af[mt][0] = cvt_tf32(a[mr * PA + kb + tig]);
                af[mt][1] = cvt_tf32(a[(mr+8) * PA + kb + tig]);
                af[mt][2] = cvt_tf32(a[mr * PA + kb + tig + 4]);
                af[mt][3] = cvt_tf32(a[(mr+8) * PA + kb + tig + 4]);
            }
            const uint4* bq = (const uint4*)(bp + ((nb2*4 + kb4)*32 + lane) * 80);
            uint4 q0 = bq[0], q1 = bq[1], q2 = bq[2], q3 = bq[3];
            uint32_t bb[16] = {q0.x,q0.y,q0.z,q0.w, q1.x,q1.y,q1.z,q1.w,
                               q2.x,q2.y,q2.z,q2.w, q3.x,q3.y,q3.z,q3.w};
#pragma unroll
            for (int mt = 0; mt < 2; mt++)
#pragma unroll
                for (int nt = 0; nt < 8; nt++)
                    mma_m16n8k8(d[mt][nt], af[mt], &bb[nt*2]);
        }
        __syncthreads();
    }

    // stage D -> smem (pitch 132), then coalesced global write
    int n0w = nb2 * 64;
#pragma unroll
    for (int mt = 0; mt < 2; mt++)
#pragma unroll
        for (int nt = 0; nt < 8; nt++) {
            int row = m0w + mt*16 + gid;
            int col = n0w + nt*8 + tig*2;
            *(float2*)&smf[row * 132 + col]       = make_float2(d[mt][nt][0], d[mt][nt][1]);
            *(float2*)&smf[(row + 8) * 132 + col] = make_float2(d[mt][nt][2], d[mt][nt][3]);
        }
    __syncthreads();
    {
        int el = tid >> 1, c0 = (tid & 1) * 64;
#pragma unroll
        for (int jv = 0; jv < 16; jv++) {
            float4 w = *(float4*)&smf[el * 132 + c0 + jv*4];
            float4 bb2 = ((const float4*)(bm + c0))[jv];
            w.x += bb2.x; w.y += bb2.y; w.z += bb2.z; w.w += bb2.w;
            *(float4*)&g_smsg[(size_t)(m0 + el) * HID + c0 + jv*4] = w;
        }
    }
}

// ---- f: f_updated + dihedral_info  (K=128, 4 chunks, N=128) ----
__global__ __launch_bounds__(256, 2)
void k_f_mma(const float* __restrict__ f, const float* __restrict__ be,
             const float* __restrict__ bd, float* __restrict__ out) {
    extern __shared__ char dsm[];
    float* smf = (float*)dsm;
    const uint32_t sbase = smem_u32(dsm);
    int tid = threadIdx.x, wid = tid >> 5, lane = tid & 31;
    int gid = lane >> 2, tig = lane & 3;
    int m0 = blockIdx.x * 128;
    int m0w = (wid & 3) * 32, nb2 = wid >> 2;
    int r = tid >> 1, s = tid & 1;

    float d[2][8][4];
#pragma unroll
    for (int mt = 0; mt < 2; mt++)
#pragma unroll
        for (int nt = 0; nt < 8; nt++)
#pragma unroll
            for (int q = 0; q < 4; q++) d[mt][nt][q] = 0.0f;

    auto issue = [&](int c) {
        int st = c & 1;
        uint32_t aDst = sbase + st * STAGE_MF2 + r * 144 + s * 64;
        const float* asrc = f + (size_t)(m0 + r) * HID + c * 32 + s * 16;
#pragma unroll
        for (int i = 0; i < 4; i++) cp16(aDst + i * 16, asrc + i * 4);
        uint32_t bBase = sbase + st * STAGE_MF2 + STAGE_A_BYTES;
        const float* bsrc = g_WeF + c * 4096;
#pragma unroll
        for (int t2 = 0; t2 < 4; t2++) {
            int g = tid + t2 * 256;
            int lb = g >> 2, i = g & 3;
            cp16(bBase + lb * 80 + i * 16, bsrc + lb * 16 + i * 4);
        }
    };

    issue(0); cp_commit();

#pragma unroll 1
    for (int c = 0; c < 4; c++) {
        if (c + 1 < 4) issue(c + 1);
        cp_commit();
        cp_wait<1>();
        __syncthreads();
        const float* a = smf + (c & 1) * (STAGE_MF2 / 4);
        const char* bp = dsm + (c & 1) * STAGE_MF2 + STAGE_A_BYTES;
#pragma unroll
        for (int kb4 = 0; kb4 < 4; kb4++) {
            int kb = kb4 * 8;
            uint32_t af[2][4];
#pragma unroll
            for (int mt = 0; mt < 2; mt++) {
                int mr = m0w + mt*16 + gid;
                af[mt][0] = cvt_tf32(a[mr * PA + kb + tig]);
                af[mt][1] = cvt_tf32(a[(mr+8) * PA + kb + tig]);
                af[mt][2] = cvt_tf32(a[mr * PA + kb + tig + 4]);
                af[mt][3] = cvt_tf32(a[(mr+8) * PA + kb + tig + 4]);
            }
            const uint4* bq = (const uint4*)(bp + ((nb2*4 + kb4)*32 + lane) * 80);
            uint4 q0 = bq[0], q1 = bq[1], q2 = bq[2], q3 = bq[3];
            uint32_t bb[16] = {q0.x,q0.y,q0.z,q0.w, q1.x,q1.y,q1.z,q1.w,
                               q2.x,q2.y,q2.z,q2.w, q3.x,q3.y,q3.z,q3.w};
#pragma unroll
            for (int mt = 0; mt < 2; mt++)
#pragma unroll
                for (int nt = 0; nt < 8; nt++)
                    mma_m16n8k8(d[mt][nt], af[mt], &bb[nt*2]);
        }
        __syncthreads();
    }

    int n0w = nb2 * 64;
#pragma unroll
    for (int mt = 0; mt < 2; mt++)
#pragma unroll
        for (int nt = 0; nt < 8; nt++) {
            int row = m0w + mt*16 + gid;
            int col = n0w + nt*8 + tig*2;
            *(float2*)&smf[row * 132 + col]       = make_float2(d[mt][nt][0], d[mt][nt][1]);
            *(float2*)&smf[(row + 8) * 132 + col] = make_float2(d[mt][nt][2], d[mt][nt][3]);
        }
    __syncthreads();
    {
        int el = tid >> 1, c0 = (tid & 1) * 64;
        int eo = m0 + el;
        float dih = g_dih[eo];
        float4 d4 = make_float4(dih, dih, dih, dih);
#pragma unroll
        for (int jv = 0; jv < 16; jv++) {
            float4 g = *(float4*)&smf[el * 132 + c0 + jv*4];
            float4 bev = ((const float4*)(be + c0))[jv];
            float4 sdv = ((const float4*)(g_Sdih + c0))[jv];
            float4 bdv = ((const float4*)(bd + c0))[jv];
            float4 fv  = *(const float4*)&f[(size_t)eo * HID + c0 + jv*4];
            float4 o;
            o.x = fv.x + (g.x + bev.x) * sigmoid_(dih * sdv.x + bdv.x);
            o.y = fv.y + (g.y + bev.y) * sigmoid_(dih * sdv.y + bdv.y);
            o.z = fv.z + (g.z + bev.z) * sigmoid_(dih * sdv.z + bdv.z);
            o.w = fv.w + (g.w + bev.w) * sigmoid_(dih * sdv.w + bdv.w);
            *(float4*)&out[OUT_F + (size_t)eo * HID + c0 + jv*4] = o;
            *(float4*)&out[OUT_DIH + (size_t)eo * HID + c0 + jv*4] = d4;
        }
    }
}

// ---- vec: 128 edges x 256 cols, 512 threads (16 warps, 4m x 4n) ----
__global__ __launch_bounds__(512, 1)
void k_vec_mma(const float* __restrict__ bvp, const float* __restrict__ v,
               const int* __restrict__ ei, float* __restrict__ out) {
    extern __shared__ char dsm[];
    float* smf = (float*)dsm;
    const uint32_t sbase = smem_u32(dsm);
    int tid = threadIdx.x, wid = tid >> 5, lane = tid & 31;
    int gid = lane >> 2, tig = lane & 3;
    int m0 = blockIdx.x * 128;
    int m0w = (wid & 3) * 32, nb4 = wid >> 2;

    float d[2][8][4];
#pragma unroll
    for (int mt = 0; mt < 2; mt++)
#pragma unroll
        for (int nt = 0; nt < 8; nt++)
#pragma unroll
            for (int q = 0; q < 4; q++) d[mt][nt][q] = 0.0f;

    auto issue = [&](int c) {
        int st = c % 3;
        uint32_t base = sbase + st * STAGE_V3;
        // A: 1024 16B-groups (128 rows x 8), 2 per thread
#pragma unroll
        for (int g2 = 0; g2 < 2; g2++) {
            int g = tid + g2 * 512;
            int row = g >> 3, i = g & 7;
            cp16(base + row * 144 + i * 16,
                 g_smsg + (size_t)(m0 + row) * HID + c * 32 + i * 4);
        }
        // B: 2048 16B-groups (512 lane-blocks x 4), 4 per thread
        const float* bsrc = g_WvF + c * 8192;
#pragma unroll
        for (int t2 = 0; t2 < 4; t2++) {
            int g = tid + t2 * 512;
            int lb = g >> 2, i = g & 3;
            cp16(base + STAGE_A_BYTES + lb * 80 + i * 16, bsrc + lb * 16 + i * 4);
        }
    };

    issue(0); cp_commit();
    issue(1); cp_commit();

#pragma unroll 1
    for (int c = 0; c < 4; c++) {
        if (c + 2 < 4) issue(c + 2);
        cp_commit();
        cp_wait<2>();
        __syncthreads();
        const float* a = smf + (c % 3) * (STAGE_V3 / 4);
        const char* bp = dsm + (c % 3) * STAGE_V3 + STAGE_A_BYTES;
#pragma unroll
        for (int kb4 = 0; kb4 < 4; kb4++) {
            int kb = kb4 * 8;
            uint32_t af[2][4];
#pragma unroll
            for (int mt = 0; mt < 2; mt++) {
                int mr = m0w + mt*16 + gid;
                af[mt][0] = cvt_tf32(a[mr * PA + kb + tig]);
                af[mt][1] = cvt_tf32(a[(mr+8) * PA + kb + tig]);
                af[mt][2] = cvt_tf32(a[mr * PA + kb + tig + 4]);
                af[mt][3] = cvt_tf32(a[(mr+8) * PA + kb + tig + 4]);
            }
            const uint4* bq = (const uint4*)(bp + ((nb4*4 + kb4)*32 + lane) * 80);
            uint4 q0 = bq[0], q1 = bq[1], q2 = bq[2], q3 = bq[3];
            uint32_t bb[16] = {q0.x,q0.y,q0.z,q0.w, q1.x,q1.y,q1.z,q1.w,
                               q2.x,q2.y,q2.z,q2.w, q3.x,q3.y,q3.z,q3.w};
#pragma unroll
            for (int mt = 0; mt < 2; mt++)
#pragma unroll
                for (int nt = 0; nt < 8; nt++)
                    mma_m16n8k8(d[mt][nt], af[mt], &bb[nt*2]);
        }
        __syncthreads();
    }

    // stage D (all 256 cols) -> smem pitch 260
    int n0w = nb4 * 64;
#pragma unroll
    for (int mt = 0; mt < 2; mt++)
#pragma unroll
        for (int nt = 0; nt < 8; nt++) {
            int row = m0w + mt*16 + gid;
            int col = n0w + nt*8 + tig*2;
            *(float2*)&smf[row * 260 + col]       = make_float2(d[mt][nt][0], d[mt][nt][1]);
            *(float2*)&smf[(row + 8) * 260 + col] = make_float2(d[mt][nt][2], d[mt][nt][3]);
        }
    __syncthreads();

    // epilogue: 4 threads per edge, float4 atomics
    {
        int el = tid >> 2, q = tid & 3;
        int eo = m0 + el;
        int rI = ei[eo], cI = ei[N_EDGES + eo];
        float4 uv = g_uvec[eo];
        float cw = uv.w;
        float ua[3] = {uv.x, uv.y, uv.z};
#pragma unroll
        for (int jv = 0; jv < 8; jv++) {
            int j0 = q*4 + jv*16;
            float4 w1 = *(float4*)&smf[el * 260 + j0];
            float4 w2 = *(float4*)&smf[el * 260 + 128 + j0];
            float4 b1 = *(const float4*)&bvp[j0];
            float4 b2 = *(const float4*)&bvp[128 + j0];
            w1.x += b1.x; w1.y += b1.y; w1.z += b1.z; w1.w += b1.w;
            w2.x += b2.x; w2.y += b2.y; w2.z += b2.z; w2.w += b2.w;
#pragma unroll
            for (int dd = 0; dd < 3; dd++) {
                float4 vv = *(const float4*)&v[((size_t)rI * 3 + dd) * HID + j0];
                float u = ua[dd];
                float4 m;
                m.x = cw * (w1.x * u + w2.x * vv.x);
                m.y = cw * (w1.y * u + w2.y * vv.y);
                m.z = cw * (w1.z * u + w2.z * vv.z);
                m.w = cw * (w1.w * u + w2.w * vv.w);
                atomicAdd((float4*)&out[OUT_V + ((size_t)cI * 3 + dd) * HID + j0], m);
            }
        }
    }
}

// ===================== launcher =====================
extern "C" void kernel_launch(void* const* d_in, const int* in_sizes, int n_in,
                              void* d_out, int out_size) {
    const float* h    = (const float*)d_in[0];
    const float* v    = (const float*)d_in[1];
    const float* f    = (const float*)d_in[2];
    const float* pos  = (const float*)d_in[3];
    const float* rbf  = (const float*)d_in[4];
    const int*   ei   = (const int*)  d_in[5];
    const float* Wm   = (const float*)d_in[6];
    const float* bm   = (const float*)d_in[7];
    const float* Wv   = (const float*)d_in[8];
    const float* bv   = (const float*)d_in[9];
    const float* Ws   = (const float*)d_in[10];
    const float* bs   = (const float*)d_in[11];
    const float* We   = (const float*)d_in[12];
    const float* be   = (const float*)d_in[13];
    const float* Wa   = (const float*)d_in[14];
    const float* ba   = (const float*)d_in[15];
    const float* Wd   = (const float*)d_in[16];
    const float* bd   = (const float*)d_in[17];
    float* out = (float*)d_out;

    const int SM_MF  = 2 * STAGE_MF2;                      // 77824 B (>= epi 67584)
    const int SM_VEC = 3 * STAGE_V3;                       // 178176 B (>= epi 133120)
    cudaFuncSetAttribute(k_msg_mma, cudaFuncAttributeMaxDynamicSharedMemorySize, SM_MF);
    cudaFuncSetAttribute(k_f_mma,   cudaFuncAttributeMaxDynamicSharedMemorySize, SM_MF);
    cudaFuncSetAttribute(k_vec_mma, cudaFuncAttributeMaxDynamicSharedMemorySize, SM_VEC);

    // Launch order: index 3 = k_msg_mma (profiled launch).
    k_colsum<<<1, 256>>>(Wa, Wd);
    k_fragpack<<<(40960 + 16384 + 32768 + 255) / 256, 256>>>(Wm, Wv, We);
    k_init<<<(2400000 + N_NODES*3 + 255) / 256, 256>>>(v, out);
    k_msg_mma<<<N_EDGES / 128, 256, SM_MF>>>(h, rbf, ei, bm);
    k_edge_geom<<<(N_EDGES + 255) / 256, 256>>>(pos, ei, out);
    k_dih<<<(N_EDGES + 255) / 256, 256>>>(ei, out);
    k_node<<<(N_NODES + 127) / 128, 256>>>(h, Ws, bs, ba, out);
    k_f_mma<<<N_EDGES / 128, 256, SM_MF>>>(f, be, bd, out);
    k_vec_mma<<<N_EDGES / 128, 512, SM_VEC>>>(bv, v, ei, out);
}